// round 9
// baseline (speedup 1.0000x reference)
#include <cuda_runtime.h>
#include <cuda_bf16.h>
#include <math.h>

// Problem constants
#define BB   2
#define NN   2048
#define MM   128
#define HH   16
#define DD   64
#define IND  1024
#define CTXD 768
#define ROWS (BB*NN)          // 4096
#define KVW  (2*HH*DD)        // 2048
#define KEXT 129              // 1 null + 128 ctx keys

// attention tiling
#define NKEYS  2240           // 2048 self + 129 ext, padded to 35*64
#define NTILES 35
#define LIMIT  2177
#define SPITCH 68

// mma gemm tiling
#define APITCH 20             // floats; (20g+t)%32 distinct -> conflict-free A frags
#define BPITCH 136            // floats; (8t+g)%32 distinct -> conflict-free B frags
#define ATILE  (128*APITCH)   // floats per A tile
#define BTILE  (16*BPITCH)    // floats per B tile

// ---------------- scratch (static device globals; no allocation) -------------
__device__ float g_xn  [ROWS*IND];
__device__ float g_q   [ROWS*HH*DD];
__device__ float g_kv  [ROWS*KVW];
__device__ float g_kext[BB*KEXT*DD];
__device__ float g_vext[BB*KEXT*DD];
__device__ float g_kt  [BB*HH*NKEYS*DD];
__device__ float g_vt  [BB*HH*DD*NKEYS];
__device__ float g_attn[ROWS*HH*DD];
__device__ float g_proj[ROWS*IND];

// ---------------- tf32 helpers -------------------------------------------------
__device__ __forceinline__ unsigned f2tf32(float x) {
    unsigned r; asm("cvt.rna.tf32.f32 %0, %1;" : "=r"(r) : "f"(x)); return r;
}
__device__ __forceinline__ float tf32f(float x) {
    return __uint_as_float(f2tf32(x));
}

#define MMA_TF32(c, a, b0_, b1_)                                               \
    asm volatile("mma.sync.aligned.m16n8k8.row.col.f32.tf32.tf32.f32 "         \
                 "{%0,%1,%2,%3}, {%4,%5,%6,%7}, {%8,%9}, {%0,%1,%2,%3};"       \
                 : "+f"((c)[0]), "+f"((c)[1]), "+f"((c)[2]), "+f"((c)[3])      \
                 : "r"((a)[0]), "r"((a)[1]), "r"((a)[2]), "r"((a)[3]),         \
                   "r"(b0_), "r"(b1_))

// ---------------- block reduction helper -------------------------------------
__device__ __forceinline__ float block_reduce_sum(float v, float* sbuf) {
    __syncthreads();
    int lane = threadIdx.x & 31, warp = threadIdx.x >> 5;
    #pragma unroll
    for (int o = 16; o; o >>= 1) v += __shfl_xor_sync(0xffffffffu, v, o);
    if (lane == 0) sbuf[warp] = v;
    __syncthreads();
    int nw = (blockDim.x + 31) >> 5;
    v = (threadIdx.x < nw) ? sbuf[threadIdx.x] : 0.0f;
    if (warp == 0) {
        #pragma unroll
        for (int o = 16; o; o >>= 1) v += __shfl_xor_sync(0xffffffffu, v, o);
        if (lane == 0) sbuf[0] = v;
    }
    __syncthreads();
    return sbuf[0];
}

// ---------------- layernorm (one block per row) -------------------------------
__global__ void ln_kernel(const float* __restrict__ in, float* __restrict__ out,
                          const float* __restrict__ g, const float* __restrict__ b,
                          int C) {
    __shared__ float sbuf[32];
    const float* x = in + (size_t)blockIdx.x * C;
    float s = 0.f, s2 = 0.f;
    for (int i = threadIdx.x; i < C; i += blockDim.x) {
        float v = x[i]; s += v; s2 += v * v;
    }
    s  = block_reduce_sum(s,  sbuf);
    s2 = block_reduce_sum(s2, sbuf);
    float mean = s / C;
    float rstd = rsqrtf(s2 / C - mean * mean + 1e-5f);
    float* o = out + (size_t)blockIdx.x * C;
    for (int i = threadIdx.x; i < C; i += blockDim.x)
        o[i] = (x[i] - mean) * rstd * g[i] + b[i];
}

// ---------------- ctx branch: LN(768) + GEMV(768x128) fused --------------------
__global__ void ctx_kernel(const float* __restrict__ c_emb,
                           const float* __restrict__ g, const float* __restrict__ b,
                           const float* __restrict__ W,
                           const float* __restrict__ bctx,
                           float* __restrict__ kext, float* __restrict__ vext) {
    __shared__ float row[CTXD];
    __shared__ float sbuf[32];
    int rid = blockIdx.x;
    int bb = rid >> 7, m = rid & 127;
    const float* x = c_emb + (size_t)rid * CTXD;
    float s = 0.f, s2 = 0.f;
    for (int i = threadIdx.x; i < CTXD; i += blockDim.x) {
        float v = x[i]; row[i] = v; s += v; s2 += v * v;
    }
    s  = block_reduce_sum(s,  sbuf);
    s2 = block_reduce_sum(s2, sbuf);
    float mean = s / CTXD;
    float rstd = rsqrtf(s2 / CTXD - mean * mean + 1e-5f);
    for (int i = threadIdx.x; i < CTXD; i += blockDim.x)
        row[i] = (row[i] - mean) * rstd * g[i] + b[i];
    __syncthreads();
    if (threadIdx.x < 128) {
        int j = threadIdx.x;
        float acc = bctx[j];
        #pragma unroll 8
        for (int d = 0; d < CTXD; d++) acc += row[d] * W[d * 128 + j];
        if (j < DD) kext[((size_t)bb * KEXT + m + 1) * DD + j] = acc;
        else        vext[((size_t)bb * KEXT + m + 1) * DD + (j - DD)] = acc;
    }
}

// ---------------- write null K/V rows -----------------------------------------
__global__ void null_kernel(const float* __restrict__ null_kv,
                            float* __restrict__ kext, float* __restrict__ vext) {
    int t = threadIdx.x;
    if (t < DD) {
        float v = null_kv[t];
        kext[0 * KEXT * DD + t] = v;
        kext[1 * KEXT * DD + t] = v;
    } else {
        int d = t - DD;
        float v = null_kv[DD + d];
        vext[0 * KEXT * DD + d] = v;
        vext[1 * KEXT * DD + d] = v;
    }
}

// ---------------- pack K and V^T into padded per-(b,h) tf32 buffers -----------
__global__ void pack_kernel(const float* __restrict__ kv,
                            const float* __restrict__ kext,
                            const float* __restrict__ vext,
                            float* __restrict__ Kp, float* __restrict__ Vt) {
    __shared__ float tile[64][65];
    int bidx = blockIdx.x;
    int kt = bidx % NTILES;
    int bh = bidx / NTILES;
    int h = bh & (HH - 1), b = bh >> 4;
    int tid = threadIdx.x;
    int tb = kt * 64;

    #pragma unroll
    for (int i = 0; i < 16; i++) {
        int idx = tid + i * 256;
        int kl = idx >> 6, d = idx & 63;
        int key = tb + kl;
        float kvval = 0.f, vvval = 0.f;
        if (key < NN) {
            const float* src = kv + ((size_t)(b * NN + key)) * KVW + h * DD + d;
            kvval = src[0];
            vvval = src[HH * DD];
        } else if (key < LIMIT) {
            size_t off = ((size_t)b * KEXT + (key - NN)) * DD + d;
            kvval = kext[off];
            vvval = vext[off];
        }
        Kp[((size_t)bh * NKEYS + key) * DD + d] = tf32f(kvval);
        tile[kl][d] = tf32f(vvval);
    }
    __syncthreads();
    #pragma unroll
    for (int i = 0; i < 16; i++) {
        int idx = tid + i * 256;
        int d = idx >> 6, kl = idx & 63;
        Vt[((size_t)bh * DD + d) * NKEYS + tb + kl] = tile[kl][d];
    }
}

// ---------------- tf32 mma GEMM: C = A(MxK) x B(KxN), row-major -----------------
// 128x128 CTA tile, BK=16, 4 warps (2x2), warp tile 64x64 (4x8 m16n8k8 frags).
// Bigger warp tiles halve smem fragment traffic vs the 8-warp 64x32 version
// (A re-read 2x instead of 4x) -- the kernel was smem-BW bound (L1 62%).
// SPLITA=1: plain tf32. SPLITA=2: A split hi/lo (2 passes) for higher accuracy.
template<int SPLITA>
__global__ __launch_bounds__(128) void mma_gemm(
        const float* __restrict__ A, const float* __restrict__ B,
        float* __restrict__ C, int M, int N, int K) {
    extern __shared__ float smf[];
    const int PER = SPLITA * ATILE + BTILE;

    int tid = threadIdx.x;
    int w = tid >> 5, lane = tid & 31, g = lane >> 2, t = lane & 3;
    int wm = (w >> 1) * 64, wn = (w & 1) * 64;

    const float* Ab = A + (size_t)(blockIdx.y * 128) * K;
    const float* Bb = B + (size_t)(blockIdx.x * 128);

    int aRow = tid;                       // each thread: one A row, 16 k-cols
    int bRow = tid >> 3, bCol = (tid & 7) * 16;  // each thread: 16 B cols of one k-row

    float acc[4][8][4];
    #pragma unroll
    for (int mi = 0; mi < 4; mi++)
        #pragma unroll
        for (int nj = 0; nj < 8; nj++)
            #pragma unroll
            for (int q = 0; q < 4; q++) acc[mi][nj][q] = 0.f;

    float4 pa[4], pb[4];
    {
        const float* ap = Ab + (size_t)aRow * K;
        const float* bp = Bb + (size_t)bRow * N + bCol;
        #pragma unroll
        for (int i = 0; i < 4; i++) {
            pa[i] = *(const float4*)(ap + i * 4);
            pb[i] = *(const float4*)(bp + i * 4);
        }
    }
    // store tile 0
    {
        float* AhP = smf;
        float* BhP = smf + SPLITA * ATILE;
        #pragma unroll
        for (int i = 0; i < 4; i++) {
            float4 h = make_float4(tf32f(pa[i].x), tf32f(pa[i].y), tf32f(pa[i].z), tf32f(pa[i].w));
            *(float4*)&AhP[aRow * APITCH + i * 4] = h;
            if (SPLITA == 2) {
                float* AlP = smf + ATILE;
                *(float4*)&AlP[aRow * APITCH + i * 4] =
                    make_float4(tf32f(pa[i].x - h.x), tf32f(pa[i].y - h.y),
                                tf32f(pa[i].z - h.z), tf32f(pa[i].w - h.w));
            }
            *(float4*)&BhP[bRow * BPITCH + bCol + i * 4] =
                make_float4(tf32f(pb[i].x), tf32f(pb[i].y), tf32f(pb[i].z), tf32f(pb[i].w));
        }
    }
    __syncthreads();

    int buf = 0;
    for (int k0 = 0; k0 < K; k0 += 16) {
        bool next = (k0 + 16) < K;
        if (next) {
            const float* ap = Ab + (size_t)aRow * K + (k0 + 16);
            const float* bp = Bb + (size_t)(k0 + 16 + bRow) * N + bCol;
            #pragma unroll
            for (int i = 0; i < 4; i++) {
                pa[i] = *(const float4*)(ap + i * 4);
                pb[i] = *(const float4*)(bp + i * 4);
            }
        }
        float* base = smf + buf * PER;
        const float* AhP = base;
        const float* AlP = base + ATILE;
        const float* BhP = base + SPLITA * ATILE;
        #pragma unroll
        for (int kk = 0; kk < 2; kk++) {
            int k = kk * 8;
            unsigned aF[4][4], bF[8][2];
            #pragma unroll
            for (int mi = 0; mi < 4; mi++) {
                const float* ap2 = AhP + (wm + mi * 16 + g) * APITCH + k + t;
                aF[mi][0] = __float_as_uint(ap2[0]);
                aF[mi][1] = __float_as_uint(ap2[8 * APITCH]);
                aF[mi][2] = __float_as_uint(ap2[4]);
                aF[mi][3] = __float_as_uint(ap2[8 * APITCH + 4]);
            }
            #pragma unroll
            for (int nj = 0; nj < 8; nj++) {
                const float* bp2 = BhP + (k + t) * BPITCH + wn + nj * 8 + g;
                bF[nj][0] = __float_as_uint(bp2[0]);
                bF[nj][1] = __float_as_uint(bp2[4 * BPITCH]);
            }
            #pragma unroll
            for (int mi = 0; mi < 4; mi++)
                #pragma unroll
                for (int nj = 0; nj < 8; nj++)
                    MMA_TF32(acc[mi][nj], aF[mi], bF[nj][0], bF[nj][1]);
            if (SPLITA == 2) {
                unsigned aL[4][4];
                #pragma unroll
                for (int mi = 0; mi < 4; mi++) {
                    const float* ap2 = AlP + (wm + mi * 16 + g) * APITCH + k + t;
                    aL[mi][0] = __float_as_uint(ap2[0]);
                    aL[mi][1] = __float_as_uint(ap2[8 * APITCH]);
                    aL[mi][2] = __float_as_uint(ap2[4]);
                    aL[mi][3] = __float_as_uint(ap2[8 * APITCH + 4]);
                }
                #pragma unroll
                for (int mi = 0; mi < 4; mi++)
                    #pragma unroll
                    for (int nj = 0; nj < 8; nj++)
                        MMA_TF32(acc[mi][nj], aL[mi], bF[nj][0], bF[nj][1]);
            }
        }
        if (next) {
            float* nb = smf + (buf ^ 1) * PER;
            float* AhP2 = nb;
            float* BhP2 = nb + SPLITA * ATILE;
            #pragma unroll
            for (int i = 0; i < 4; i++) {
                float4 h = make_float4(tf32f(pa[i].x), tf32f(pa[i].y), tf32f(pa[i].z), tf32f(pa[i].w));
                *(float4*)&AhP2[aRow * APITCH + i * 4] = h;
                if (SPLITA == 2) {
                    float* AlP2 = nb + ATILE;
                    *(float4*)&AlP2[aRow * APITCH + i * 4] =
                        make_float4(tf32f(pa[i].x - h.x), tf32f(pa[i].y - h.y),
                                    tf32f(pa[i].z - h.z), tf32f(pa[i].w - h.w));
                }
                *(float4*)&BhP2[bRow * BPITCH + bCol + i * 4] =
                    make_float4(tf32f(pb[i].x), tf32f(pb[i].y), tf32f(pb[i].z), tf32f(pb[i].w));
            }
            __syncthreads();
            buf ^= 1;
        }
    }

    #pragma unroll
    for (int mi = 0; mi < 4; mi++) {
        int row = blockIdx.y * 128 + wm + mi * 16 + g;
        #pragma unroll
        for (int nj = 0; nj < 8; nj++) {
            int col = blockIdx.x * 128 + wn + nj * 8 + 2 * t;
            *(float2*)&C[(size_t)row * N + col]       = make_float2(acc[mi][nj][0], acc[mi][nj][1]);
            *(float2*)&C[(size_t)(row + 8) * N + col] = make_float2(acc[mi][nj][2], acc[mi][nj][3]);
        }
    }
}

// ---------------- flash attention on tensor cores (tf32 mma.sync) --------------
__global__ __launch_bounds__(128) void attn_mma_kernel(
        const float* __restrict__ qb,
        const float* __restrict__ Kp,
        const float* __restrict__ Vt,
        float* __restrict__ outb) {
    __shared__ float Ksm[64 * SPITCH];
    __shared__ float Vsm[64 * SPITCH];
    int b = blockIdx.z, h = blockIdx.y;
    int tid = threadIdx.x;
    int w = tid >> 5, lane = tid & 31;
    int g = lane >> 2, t = lane & 3;
    int qa = blockIdx.x * 64 + w * 16 + g;

    unsigned qA[8][4];
    {
        const float* q0 = qb + ((size_t)(b * NN + qa)) * (HH * DD) + h * DD;
        const float* q1 = q0 + 8 * (HH * DD);
        #pragma unroll
        for (int kk = 0; kk < 8; kk++) {
            qA[kk][0] = f2tf32(q0[kk * 8 + t]     * 0.125f);
            qA[kk][1] = f2tf32(q1[kk * 8 + t]     * 0.125f);
            qA[kk][2] = f2tf32(q0[kk * 8 + t + 4] * 0.125f);
            qA[kk][3] = f2tf32(q1[kk * 8 + t + 4] * 0.125f);
        }
    }

    const float* Kg = Kp + ((size_t)(b * HH + h)) * NKEYS * DD;
    const float* Vg = Vt + ((size_t)(b * HH + h)) * DD * NKEYS;

    float m0 = -1e30f, m1 = -1e30f, l0 = 0.f, l1 = 0.f;
    float oC[8][4];
    #pragma unroll
    for (int nt = 0; nt < 8; nt++)
        #pragma unroll
        for (int j = 0; j < 4; j++) oC[nt][j] = 0.f;

    float* Prow0 = &Ksm[(w * 16 + g)     * SPITCH];
    float* Prow1 = &Ksm[(w * 16 + g + 8) * SPITCH];

    for (int tile = 0; tile < NTILES; tile++) {
        int tb = tile * 64;
        __syncthreads();
        #pragma unroll
        for (int i = 0; i < 8; i++) {
            int idx = tid + i * 128;
            int r = idx >> 4, c = (idx & 15) * 4;
            *(float4*)&Ksm[r * SPITCH + c] = *(const float4*)&Kg[(size_t)(tb + r) * DD + c];
            *(float4*)&Vsm[r * SPITCH + c] = *(const float4*)&Vg[(size_t)r * NKEYS + tb + c];
        }
        __syncthreads();

        float sC[8][4];
        #pragma unroll
        for (int nt = 0; nt < 8; nt++)
            #pragma unroll
            for (int j = 0; j < 4; j++) sC[nt][j] = 0.f;
        #pragma unroll
        for (int kk = 0; kk < 8; kk++) {
            #pragma unroll
            for (int nt = 0; nt < 8; nt++) {
                const float* kr = &Ksm[(nt * 8 + g) * SPITCH + kk * 8 + t];
                unsigned b0 = __float_as_uint(kr[0]);
                unsigned b1 = __float_as_uint(kr[4]);
                MMA_TF32(sC[nt], qA[kk], b0, b1);
            }
        }

        int lim = LIMIT - tb;
        float tmax0 = -1e30f, tmax1 = -1e30f;
        #pragma unroll
        for (int nt = 0; nt < 8; nt++) {
            int c0 = nt * 8 + 2 * t, c1 = c0 + 1;
            if (c0 >= lim) { sC[nt][0] = -1e30f; sC[nt][2] = -1e30f; }
            if (c1 >= lim) { sC[nt][1] = -1e30f; sC[nt][3] = -1e30f; }
            tmax0 = fmaxf(tmax0, fmaxf(sC[nt][0], sC[nt][1]));
            tmax1 = fmaxf(tmax1, fmaxf(sC[nt][2], sC[nt][3]));
        }
        tmax0 = fmaxf(tmax0, __shfl_xor_sync(0xffffffffu, tmax0, 1));
        tmax0 = fmaxf(tmax0, __shfl_xor_sync(0xffffffffu, tmax0, 2));
        tmax1 = fmaxf(tmax1, __shfl_xor_sync(0xffffffffu, tmax1, 1));
        tmax1 = fmaxf(tmax1, __shfl_xor_sync(0xffffffffu, tmax1, 2));

        float mn0 = fmaxf(m0, tmax0), mn1 = fmaxf(m1, tmax1);
        float corr0 = __expf(m0 - mn0), corr1 = __expf(m1 - mn1);
        m0 = mn0; m1 = mn1;

        __syncthreads();
        float ps0 = 0.f, ps1 = 0.f;
        #pragma unroll
        for (int nt = 0; nt < 8; nt++) {
            float p0 = __expf(sC[nt][0] - m0), p1 = __expf(sC[nt][1] - m0);
            float p2 = __expf(sC[nt][2] - m1), p3 = __expf(sC[nt][3] - m1);
            ps0 += p0 + p1; ps1 += p2 + p3;
            *(float2*)&Prow0[nt * 8 + 2 * t] = make_float2(tf32f(p0), tf32f(p1));
            *(float2*)&Prow1[nt * 8 + 2 * t] = make_float2(tf32f(p2), tf32f(p3));
            oC[nt][0] *= corr0; oC[nt][1] *= corr0;
            oC[nt][2] *= corr1; oC[nt][3] *= corr1;
        }
        l0 = l0 * corr0 + ps0;
        l1 = l1 * corr1 + ps1;
        __syncwarp();

        #pragma unroll
        for (int kk = 0; kk < 8; kk++) {
            unsigned a[4];
            a[0] = __float_as_uint(Prow0[kk * 8 + t]);
            a[1] = __float_as_uint(Prow1[kk * 8 + t]);
            a[2] = __float_as_uint(Prow0[kk * 8 + t + 4]);
            a[3] = __float_as_uint(Prow1[kk * 8 + t + 4]);
            #pragma unroll
            for (int nd = 0; nd < 8; nd++) {
                const float* vr = &Vsm[(nd * 8 + g) * SPITCH + kk * 8 + t];
                unsigned b0 = __float_as_uint(vr[0]);
                unsigned b1 = __float_as_uint(vr[4]);
                MMA_TF32(oC[nd], a, b0, b1);
            }
        }
    }

    l0 += __shfl_xor_sync(0xffffffffu, l0, 1);
    l0 += __shfl_xor_sync(0xffffffffu, l0, 2);
    l1 += __shfl_xor_sync(0xffffffffu, l1, 1);
    l1 += __shfl_xor_sync(0xffffffffu, l1, 2);
    float inv0 = 1.f / l0, inv1 = 1.f / l1;
    float* o0 = outb + ((size_t)(b * NN + qa)) * (HH * DD) + h * DD;
    float* o1 = o0 + 8 * (HH * DD);
    #pragma unroll
    for (int nt = 0; nt < 8; nt++) {
        *(float2*)&o0[nt * 8 + 2 * t] = make_float2(oC[nt][0] * inv0, oC[nt][1] * inv0);
        *(float2*)&o1[nt * 8 + 2 * t] = make_float2(oC[nt][2] * inv1, oC[nt][3] * inv1);
    }
}

// ---------------- host launcher ------------------------------------------------
extern "C" void kernel_launch(void* const* d_in, const int* in_sizes, int n_in,
                              void* d_out, int out_size) {
    const float* x        = (const float*)d_in[0];
    const float* c_emb    = (const float*)d_in[1];
    const float* ln_g     = (const float*)d_in[2];
    const float* ln_b     = (const float*)d_in[3];
    const float* ctx_ln_g = (const float*)d_in[4];
    const float* ctx_ln_b = (const float*)d_in[5];
    const float* W_ctx    = (const float*)d_in[6];
    const float* b_ctx    = (const float*)d_in[7];
    const float* W_q      = (const float*)d_in[8];
    const float* W_kv     = (const float*)d_in[9];
    const float* null_kv  = (const float*)d_in[10];
    const float* W_out    = (const float*)d_in[11];
    const float* out_ln_g = (const float*)d_in[12];
    const float* out_ln_b = (const float*)d_in[13];
    float* out = (float*)d_out;

    float *xn, *qb, *kvb, *kext, *vext, *kt, *vt, *attn, *proj;
    cudaGetSymbolAddress((void**)&xn,   g_xn);
    cudaGetSymbolAddress((void**)&qb,   g_q);
    cudaGetSymbolAddress((void**)&kvb,  g_kv);
    cudaGetSymbolAddress((void**)&kext, g_kext);
    cudaGetSymbolAddress((void**)&vext, g_vext);
    cudaGetSymbolAddress((void**)&kt,   g_kt);
    cudaGetSymbolAddress((void**)&vt,   g_vt);
    cudaGetSymbolAddress((void**)&attn, g_attn);
    cudaGetSymbolAddress((void**)&proj, g_proj);

    const int smem1 = 2 * (1 * ATILE + BTILE) * 4;   // 37888 B
    const int smem2 = 2 * (2 * ATILE + BTILE) * 4;   // 58368 B
    cudaFuncSetAttribute(mma_gemm<1>, cudaFuncAttributeMaxDynamicSharedMemorySize, smem1);
    cudaFuncSetAttribute(mma_gemm<2>, cudaFuncAttributeMaxDynamicSharedMemorySize, smem2);

    ln_kernel<<<ROWS, 256>>>(x, xn, ln_g, ln_b, IND);
    ctx_kernel<<<BB * MM, 256>>>(c_emb, ctx_ln_g, ctx_ln_b, W_ctx, b_ctx, kext, vext);
    null_kernel<<<1, 128>>>(null_kv, kext, vext);
    mma_gemm<1><<<dim3((HH * DD) / 128, ROWS / 128), 128, smem1>>>(xn, W_q,  qb,  ROWS, HH * DD, IND);
    mma_gemm<1><<<dim3(KVW / 128,       ROWS / 128), 128, smem1>>>(xn, W_kv, kvb, ROWS, KVW,     IND);
    pack_kernel<<<BB * HH * NTILES, 256>>>(kvb, kext, vext, kt, vt);
    attn_mma_kernel<<<dim3(NN / 64, HH, BB), 128>>>(qb, kt, vt, attn);
    mma_gemm<2><<<dim3(IND / 128, ROWS / 128), 128, smem2>>>(attn, W_out, proj, ROWS, IND, IND);
    ln_kernel<<<ROWS, 256>>>(proj, out, out_ln_g, out_ln_b, IND);
}

// round 11
// speedup vs baseline: 1.0710x; 1.0710x over previous
#include <cuda_runtime.h>
#include <cuda_bf16.h>
#include <math.h>

// Problem constants
#define BB   2
#define NN   2048
#define MM   128
#define HH   16
#define DD   64
#define IND  1024
#define CTXD 768
#define ROWS (BB*NN)          // 4096
#define KVW  (2*HH*DD)        // 2048
#define KEXT 129              // 1 null + 128 ctx keys

// attention tiling
#define NKEYS  2240           // 2048 self + 129 ext, padded to 35*64
#define NTILES 35
#define LIMIT  2177
#define SPITCH 68

// mma gemm tiling (R6-proven: 8 warps, 64x32 warp tiles, 256 threads)
#define APITCH 20             // floats; (20g+t)%32 distinct -> conflict-free A frags
#define BPITCH 136            // floats; (8t+g)%32 distinct -> conflict-free B frags
#define ATILE  (128*APITCH)   // floats per A tile
#define BTILE  (16*BPITCH)    // floats per B tile

// ---------------- scratch (static device globals; no allocation) -------------
__device__ float g_xn  [ROWS*IND];
__device__ float g_q   [ROWS*HH*DD];
__device__ float g_kext[BB*KEXT*DD];
__device__ float g_vext[BB*KEXT*DD];
__device__ float g_kt  [BB*HH*NKEYS*DD];   // K packed  [b][h][key][d]  (tf32 bits)
__device__ float g_vt  [BB*HH*DD*NKEYS];   // V^T packed [b][h][d][key] (tf32 bits)
__device__ float g_attn[ROWS*HH*DD];
__device__ float g_proj[ROWS*IND];

// ---------------- tf32 helpers -------------------------------------------------
__device__ __forceinline__ unsigned f2tf32(float x) {
    unsigned r; asm("cvt.rna.tf32.f32 %0, %1;" : "=r"(r) : "f"(x)); return r;
}
__device__ __forceinline__ float tf32f(float x) {
    return __uint_as_float(f2tf32(x));
}

#define MMA_TF32(c, a, b0_, b1_)                                               \
    asm volatile("mma.sync.aligned.m16n8k8.row.col.f32.tf32.tf32.f32 "         \
                 "{%0,%1,%2,%3}, {%4,%5,%6,%7}, {%8,%9}, {%0,%1,%2,%3};"       \
                 : "+f"((c)[0]), "+f"((c)[1]), "+f"((c)[2]), "+f"((c)[3])      \
                 : "r"((a)[0]), "r"((a)[1]), "r"((a)[2]), "r"((a)[3]),         \
                   "r"(b0_), "r"(b1_))

// ---------------- block reduction helper -------------------------------------
__device__ __forceinline__ float block_reduce_sum(float v, float* sbuf) {
    __syncthreads();
    int lane = threadIdx.x & 31, warp = threadIdx.x >> 5;
    #pragma unroll
    for (int o = 16; o; o >>= 1) v += __shfl_xor_sync(0xffffffffu, v, o);
    if (lane == 0) sbuf[warp] = v;
    __syncthreads();
    int nw = (blockDim.x + 31) >> 5;
    v = (threadIdx.x < nw) ? sbuf[threadIdx.x] : 0.0f;
    if (warp == 0) {
        #pragma unroll
        for (int o = 16; o; o >>= 1) v += __shfl_xor_sync(0xffffffffu, v, o);
        if (lane == 0) sbuf[0] = v;
    }
    __syncthreads();
    return sbuf[0];
}

// ---------------- layernorm (one block per row) -------------------------------
__global__ void ln_kernel(const float* __restrict__ in, float* __restrict__ out,
                          const float* __restrict__ g, const float* __restrict__ b,
                          int C) {
    __shared__ float sbuf[32];
    const float* x = in + (size_t)blockIdx.x * C;
    float s = 0.f, s2 = 0.f;
    for (int i = threadIdx.x; i < C; i += blockDim.x) {
        float v = x[i]; s += v; s2 += v * v;
    }
    s  = block_reduce_sum(s,  sbuf);
    s2 = block_reduce_sum(s2, sbuf);
    float mean = s / C;
    float rstd = rsqrtf(s2 / C - mean * mean + 1e-5f);
    float* o = out + (size_t)blockIdx.x * C;
    for (int i = threadIdx.x; i < C; i += blockDim.x)
        o[i] = (x[i] - mean) * rstd * g[i] + b[i];
}

// ---------------- ctx branch: LN(768) + GEMV(768x128) fused --------------------
__global__ void ctx_kernel(const float* __restrict__ c_emb,
                           const float* __restrict__ g, const float* __restrict__ b,
                           const float* __restrict__ W,
                           const float* __restrict__ bctx,
                           float* __restrict__ kext, float* __restrict__ vext) {
    __shared__ float row[CTXD];
    __shared__ float sbuf[32];
    int rid = blockIdx.x;
    int bb = rid >> 7, m = rid & 127;
    const float* x = c_emb + (size_t)rid * CTXD;
    float s = 0.f, s2 = 0.f;
    for (int i = threadIdx.x; i < CTXD; i += blockDim.x) {
        float v = x[i]; row[i] = v; s += v; s2 += v * v;
    }
    s  = block_reduce_sum(s,  sbuf);
    s2 = block_reduce_sum(s2, sbuf);
    float mean = s / CTXD;
    float rstd = rsqrtf(s2 / CTXD - mean * mean + 1e-5f);
    for (int i = threadIdx.x; i < CTXD; i += blockDim.x)
        row[i] = (row[i] - mean) * rstd * g[i] + b[i];
    __syncthreads();
    if (threadIdx.x < 128) {
        int j = threadIdx.x;
        float acc = bctx[j];
        #pragma unroll 8
        for (int d = 0; d < CTXD; d++) acc += row[d] * W[d * 128 + j];
        if (j < DD) kext[((size_t)bb * KEXT + m + 1) * DD + j] = acc;
        else        vext[((size_t)bb * KEXT + m + 1) * DD + (j - DD)] = acc;
    }
}

// ---------------- write null K/V rows -----------------------------------------
__global__ void null_kernel(const float* __restrict__ null_kv,
                            float* __restrict__ kext, float* __restrict__ vext) {
    int t = threadIdx.x;
    if (t < DD) {
        float v = null_kv[t];
        kext[0 * KEXT * DD + t] = v;
        kext[1 * KEXT * DD + t] = v;
    } else {
        int d = t - DD;
        float v = null_kv[DD + d];
        vext[0 * KEXT * DD + d] = v;
        vext[1 * KEXT * DD + d] = v;
    }
}

// ---------------- pack EXT region (keys 2048..2239) into Kp / Vt ---------------
// grid = B*H blocks, 256 threads. Also zeros the pad tail (keys >= LIMIT).
__global__ void pack_ext_kernel(const float* __restrict__ kext,
                                const float* __restrict__ vext,
                                float* __restrict__ Kp, float* __restrict__ Vt) {
    int bh = blockIdx.x;
    int b = bh >> 4;
    int tid = threadIdx.x;
    const int NE = NKEYS - NN;            // 192 ext+pad keys
    for (int idx = tid; idx < NE * DD; idx += 256) {
        int kl = idx / DD, d = idx % DD;  // kl: 0..191
        int key = NN + kl;
        float kvval = 0.f, vvval = 0.f;
        if (key < LIMIT) {
            size_t off = ((size_t)b * KEXT + kl) * DD + d;
            kvval = tf32f(kext[off]);
            vvval = tf32f(vext[off]);
        }
        Kp[((size_t)bh * NKEYS + key) * DD + d] = kvval;
        Vt[((size_t)bh * DD + d) * NKEYS + key] = vvval;
    }
}

// ---------------- tf32 mma GEMM: C = A(MxK) x B(KxN), row-major -----------------
// R6-proven config: 128x128 CTA tile, BK=16, 8 warps (2x4), warp tile 64x32.
// SPLITA=1: plain tf32. SPLITA=2: A split hi/lo (2 passes) for higher accuracy.
// MODE=0: write C.  MODE=1: KV-pack epilogue -> write Kp (k half) / Vt (v half)
// with tf32 rounding; C not written.
template<int SPLITA, int MODE>
__global__ __launch_bounds__(256) void mma_gemm(
        const float* __restrict__ A, const float* __restrict__ B,
        float* __restrict__ C, int M, int N, int K,
        float* __restrict__ Kp, float* __restrict__ Vt) {
    extern __shared__ float smf[];
    const int PER = SPLITA * ATILE + BTILE;

    int tid = threadIdx.x;
    int w = tid >> 5, lane = tid & 31, g = lane >> 2, t = lane & 3;
    int wm = (w >> 2) * 64, wn = (w & 3) * 32;

    const float* Ab = A + (size_t)(blockIdx.y * 128) * K;
    const float* Bb = B + (size_t)(blockIdx.x * 128);

    int aRow = tid >> 1,  aCol = (tid & 1) * 8;
    int bRow = tid >> 4,  bCol = (tid & 15) * 8;

    float acc[4][4][4];
    #pragma unroll
    for (int mi = 0; mi < 4; mi++)
        #pragma unroll
        for (int nj = 0; nj < 4; nj++)
            #pragma unroll
            for (int q = 0; q < 4; q++) acc[mi][nj][q] = 0.f;

    float4 pa0, pa1, pb0, pb1;
    {
        const float* ap = Ab + (size_t)aRow * K + aCol;
        pa0 = *(const float4*)ap; pa1 = *(const float4*)(ap + 4);
        const float* bp = Bb + (size_t)bRow * N + bCol;
        pb0 = *(const float4*)bp; pb1 = *(const float4*)(bp + 4);
    }
    // store tile 0
    {
        float* base = smf;
        float* AhP = base;
        float* BhP = base + SPLITA * ATILE;
        float4 h0 = make_float4(tf32f(pa0.x), tf32f(pa0.y), tf32f(pa0.z), tf32f(pa0.w));
        float4 h1 = make_float4(tf32f(pa1.x), tf32f(pa1.y), tf32f(pa1.z), tf32f(pa1.w));
        *(float4*)&AhP[aRow * APITCH + aCol]     = h0;
        *(float4*)&AhP[aRow * APITCH + aCol + 4] = h1;
        if (SPLITA == 2) {
            float* AlP = base + ATILE;
            *(float4*)&AlP[aRow * APITCH + aCol] =
                make_float4(tf32f(pa0.x - h0.x), tf32f(pa0.y - h0.y), tf32f(pa0.z - h0.z), tf32f(pa0.w - h0.w));
            *(float4*)&AlP[aRow * APITCH + aCol + 4] =
                make_float4(tf32f(pa1.x - h1.x), tf32f(pa1.y - h1.y), tf32f(pa1.z - h1.z), tf32f(pa1.w - h1.w));
        }
        *(float4*)&BhP[bRow * BPITCH + bCol] =
            make_float4(tf32f(pb0.x), tf32f(pb0.y), tf32f(pb0.z), tf32f(pb0.w));
        *(float4*)&BhP[bRow * BPITCH + bCol + 4] =
            make_float4(tf32f(pb1.x), tf32f(pb1.y), tf32f(pb1.z), tf32f(pb1.w));
    }
    __syncthreads();

    int buf = 0;
    for (int k0 = 0; k0 < K; k0 += 16) {
        bool next = (k0 + 16) < K;
        if (next) {
            const float* ap = Ab + (size_t)aRow * K + (k0 + 16) + aCol;
            pa0 = *(const float4*)ap; pa1 = *(const float4*)(ap + 4);
            const float* bp = Bb + (size_t)(k0 + 16 + bRow) * N + bCol;
            pb0 = *(const float4*)bp; pb1 = *(const float4*)(bp + 4);
        }
        float* base = smf + buf * PER;
        const float* AhP = base;
        const float* AlP = base + ATILE;
        const float* BhP = base + SPLITA * ATILE;
        #pragma unroll
        for (int kk = 0; kk < 2; kk++) {
            int k = kk * 8;
            unsigned aF[4][4], bF[4][2];
            #pragma unroll
            for (int mi = 0; mi < 4; mi++) {
                const float* ap2 = AhP + (wm + mi * 16 + g) * APITCH + k + t;
                aF[mi][0] = __float_as_uint(ap2[0]);
                aF[mi][1] = __float_as_uint(ap2[8 * APITCH]);
                aF[mi][2] = __float_as_uint(ap2[4]);
                aF[mi][3] = __float_as_uint(ap2[8 * APITCH + 4]);
            }
            #pragma unroll
            for (int nj = 0; nj < 4; nj++) {
                const float* bp2 = BhP + (k + t) * BPITCH + wn + nj * 8 + g;
                bF[nj][0] = __float_as_uint(bp2[0]);
                bF[nj][1] = __float_as_uint(bp2[4 * BPITCH]);
            }
            #pragma unroll
            for (int mi = 0; mi < 4; mi++)
                #pragma unroll
                for (int nj = 0; nj < 4; nj++)
                    MMA_TF32(acc[mi][nj], aF[mi], bF[nj][0], bF[nj][1]);
            if (SPLITA == 2) {
                unsigned aL[4][4];
                #pragma unroll
                for (int mi = 0; mi < 4; mi++) {
                    const float* ap2 = AlP + (wm + mi * 16 + g) * APITCH + k + t;
                    aL[mi][0] = __float_as_uint(ap2[0]);
                    aL[mi][1] = __float_as_uint(ap2[8 * APITCH]);
                    aL[mi][2] = __float_as_uint(ap2[4]);
                    aL[mi][3] = __float_as_uint(ap2[8 * APITCH + 4]);
                }
                #pragma unroll
                for (int mi = 0; mi < 4; mi++)
                    #pragma unroll
                    for (int nj = 0; nj < 4; nj++)
                        MMA_TF32(acc[mi][nj], aL[mi], bF[nj][0], bF[nj][1]);
            }
        }
        if (next) {
            float* nb = smf + (buf ^ 1) * PER;
            float* AhP2 = nb;
            float* BhP2 = nb + SPLITA * ATILE;
            float4 h0 = make_float4(tf32f(pa0.x), tf32f(pa0.y), tf32f(pa0.z), tf32f(pa0.w));
            float4 h1 = make_float4(tf32f(pa1.x), tf32f(pa1.y), tf32f(pa1.z), tf32f(pa1.w));
            *(float4*)&AhP2[aRow * APITCH + aCol]     = h0;
            *(float4*)&AhP2[aRow * APITCH + aCol + 4] = h1;
            if (SPLITA == 2) {
                float* AlP2 = nb + ATILE;
                *(float4*)&AlP2[aRow * APITCH + aCol] =
                    make_float4(tf32f(pa0.x - h0.x), tf32f(pa0.y - h0.y), tf32f(pa0.z - h0.z), tf32f(pa0.w - h0.w));
                *(float4*)&AlP2[aRow * APITCH + aCol + 4] =
                    make_float4(tf32f(pa1.x - h1.x), tf32f(pa1.y - h1.y), tf32f(pa1.z - h1.z), tf32f(pa1.w - h1.w));
            }
            *(float4*)&BhP2[bRow * BPITCH + bCol] =
                make_float4(tf32f(pb0.x), tf32f(pb0.y), tf32f(pb0.z), tf32f(pb0.w));
            *(float4*)&BhP2[bRow * BPITCH + bCol + 4] =
                make_float4(tf32f(pb1.x), tf32f(pb1.y), tf32f(pb1.z), tf32f(pb1.w));
            __syncthreads();
            buf ^= 1;
        }
    }

    if (MODE == 0) {
        #pragma unroll
        for (int mi = 0; mi < 4; mi++) {
            int row = blockIdx.y * 128 + wm + mi * 16 + g;
            #pragma unroll
            for (int nj = 0; nj < 4; nj++) {
                int col = blockIdx.x * 128 + wn + nj * 8 + 2 * t;
                *(float2*)&C[(size_t)row * N + col]       = make_float2(acc[mi][nj][0], acc[mi][nj][1]);
                *(float2*)&C[(size_t)(row + 8) * N + col] = make_float2(acc[mi][nj][2], acc[mi][nj][3]);
            }
        }
    } else {
        // KV pack epilogue: row = token, col -> (s, h, d); write Kp / Vt (tf32).
        #pragma unroll
        for (int mi = 0; mi < 4; mi++) {
            int row = blockIdx.y * 128 + wm + mi * 16 + g;
            #pragma unroll
            for (int nj = 0; nj < 4; nj++) {
                int col = blockIdx.x * 128 + wn + nj * 8 + 2 * t;
                int s = col >> 10, h = (col >> 6) & 15, d = col & 63;
                #pragma unroll
                for (int half = 0; half < 2; half++) {
                    int tok = row + half * 8;
                    int b = tok >> 11, n = tok & 2047;
                    int bh = b * HH + h;
                    float v0 = tf32f(acc[mi][nj][half * 2 + 0]);
                    float v1 = tf32f(acc[mi][nj][half * 2 + 1]);
                    if (s == 0) {
                        *(float2*)&Kp[((size_t)bh * NKEYS + n) * DD + d] = make_float2(v0, v1);
                    } else {
                        Vt[((size_t)bh * DD + d)     * NKEYS + n] = v0;
                        Vt[((size_t)bh * DD + d + 1) * NKEYS + n] = v1;
                    }
                }
            }
        }
    }
}

// ---------------- flash attention on tensor cores (tf32 mma.sync) --------------
// grid (N/128, H, B), 256 threads = 8 warps; each warp owns 16 query rows.
// K/V tiles (64 keys) shared by all 8 warps; P in its own smem buffer.
__global__ __launch_bounds__(256) void attn_mma_kernel(
        const float* __restrict__ qb,
        const float* __restrict__ Kp,
        const float* __restrict__ Vt,
        float* __restrict__ outb) {
    extern __shared__ float smem[];
    float* Ksm = smem;                    // 64 * SPITCH
    float* Vsm = smem + 64 * SPITCH;      // 64 * SPITCH
    float* Psm = smem + 128 * SPITCH;     // 128 * SPITCH (per-warp-private rows)
    int b = blockIdx.z, h = blockIdx.y;
    int tid = threadIdx.x;
    int w = tid >> 5, lane = tid & 31;
    int g = lane >> 2, t = lane & 3;
    int qa = blockIdx.x * 128 + w * 16 + g;

    unsigned qA[8][4];
    {
        const float* q0 = qb + ((size_t)(b * NN + qa)) * (HH * DD) + h * DD;
        const float* q1 = q0 + 8 * (HH * DD);
        #pragma unroll
        for (int kk = 0; kk < 8; kk++) {
            qA[kk][0] = f2tf32(q0[kk * 8 + t]     * 0.125f);
            qA[kk][1] = f2tf32(q1[kk * 8 + t]     * 0.125f);
            qA[kk][2] = f2tf32(q0[kk * 8 + t + 4] * 0.125f);
            qA[kk][3] = f2tf32(q1[kk * 8 + t + 4] * 0.125f);
        }
    }

    const float* Kg = Kp + ((size_t)(b * HH + h)) * NKEYS * DD;
    const float* Vg = Vt + ((size_t)(b * HH + h)) * DD * NKEYS;

    float m0 = -1e30f, m1 = -1e30f, l0 = 0.f, l1 = 0.f;
    float oC[8][4];
    #pragma unroll
    for (int nt = 0; nt < 8; nt++)
        #pragma unroll
        for (int j = 0; j < 4; j++) oC[nt][j] = 0.f;

    float* Prow0 = &Psm[(w * 16 + g)     * SPITCH];
    float* Prow1 = &Psm[(w * 16 + g + 8) * SPITCH];

    for (int tile = 0; tile < NTILES; tile++) {
        int tb = tile * 64;
        __syncthreads();               // all warps done with prev K/V tiles
        #pragma unroll
        for (int i = 0; i < 4; i++) {
            int idx = tid + i * 256;   // 0..1023
            int r = idx >> 4, c = (idx & 15) * 4;
            *(float4*)&Ksm[r * SPITCH + c] = *(const float4*)&Kg[(size_t)(tb + r) * DD + c];
            *(float4*)&Vsm[r * SPITCH + c] = *(const float4*)&Vg[(size_t)r * NKEYS + tb + c];
        }
        __syncthreads();

        float sC[8][4];
        #pragma unroll
        for (int nt = 0; nt < 8; nt++)
            #pragma unroll
            for (int j = 0; j < 4; j++) sC[nt][j] = 0.f;
        #pragma unroll
        for (int kk = 0; kk < 8; kk++) {
            #pragma unroll
            for (int nt = 0; nt < 8; nt++) {
                const float* kr = &Ksm[(nt * 8 + g) * SPITCH + kk * 8 + t];
                unsigned b0 = __float_as_uint(kr[0]);
                unsigned b1 = __float_as_uint(kr[4]);
                MMA_TF32(sC[nt], qA[kk], b0, b1);
            }
        }

        int lim = LIMIT - tb;
        float tmax0 = -1e30f, tmax1 = -1e30f;
        #pragma unroll
        for (int nt = 0; nt < 8; nt++) {
            int c0 = nt * 8 + 2 * t, c1 = c0 + 1;
            if (c0 >= lim) { sC[nt][0] = -1e30f; sC[nt][2] = -1e30f; }
            if (c1 >= lim) { sC[nt][1] = -1e30f; sC[nt][3] = -1e30f; }
            tmax0 = fmaxf(tmax0, fmaxf(sC[nt][0], sC[nt][1]));
            tmax1 = fmaxf(tmax1, fmaxf(sC[nt][2], sC[nt][3]));
        }
        tmax0 = fmaxf(tmax0, __shfl_xor_sync(0xffffffffu, tmax0, 1));
        tmax0 = fmaxf(tmax0, __shfl_xor_sync(0xffffffffu, tmax0, 2));
        tmax1 = fmaxf(tmax1, __shfl_xor_sync(0xffffffffu, tmax1, 1));
        tmax1 = fmaxf(tmax1, __shfl_xor_sync(0xffffffffu, tmax1, 2));

        float mn0 = fmaxf(m0, tmax0), mn1 = fmaxf(m1, tmax1);
        float corr0 = __expf(m0 - mn0), corr1 = __expf(m1 - mn1);
        m0 = mn0; m1 = mn1;

        float ps0 = 0.f, ps1 = 0.f;
        #pragma unroll
        for (int nt = 0; nt < 8; nt++) {
            float p0 = __expf(sC[nt][0] - m0), p1 = __expf(sC[nt][1] - m0);
            float p2 = __expf(sC[nt][2] - m1), p3 = __expf(sC[nt][3] - m1);
            ps0 += p0 + p1; ps1 += p2 + p3;
            *(float2*)&Prow0[nt * 8 + 2 * t] = make_float2(tf32f(p0), tf32f(p1));
            *(float2*)&Prow1[nt * 8 + 2 * t] = make_float2(tf32f(p2), tf32f(p3));
            oC[nt][0] *= corr0; oC[nt][1] *= corr0;
            oC[nt][2] *= corr1; oC[nt][3] *= corr1;
        }
        l0 = l0 * corr0 + ps0;
        l1 = l1 * corr1 + ps1;
        __syncwarp();                  // P rows are warp-private

        #pragma unroll
        for (int kk = 0; kk < 8; kk++) {
            unsigned a[4];
            a[0] = __float_as_uint(Prow0[kk * 8 + t]);
            a[1] = __float_as_uint(Prow1[kk * 8 + t]);
            a[2] = __float_as_uint(Prow0[kk * 8 + t + 4]);
            a[3] = __float_as_uint(Prow1[kk * 8 + t + 4]);
            #pragma unroll
            for (int nd = 0; nd < 8; nd++) {
                const float* vr = &Vsm[(nd * 8 + g) * SPITCH + kk * 8 + t];
                unsigned b0 = __float_as_uint(vr[0]);
                unsigned b1 = __float_as_uint(vr[4]);
                MMA_TF32(oC[nd], a, b0, b1);
            }
        }
    }

    l0 += __shfl_xor_sync(0xffffffffu, l0, 1);
    l0 += __shfl_xor_sync(0xffffffffu, l0, 2);
    l1 += __shfl_xor_sync(0xffffffffu, l1, 1);
    l1 += __shfl_xor_sync(0xffffffffu, l1, 2);
    float inv0 = 1.f / l0, inv1 = 1.f / l1;
    float* o0 = outb + ((size_t)(b * NN + qa)) * (HH * DD) + h * DD;
    float* o1 = o0 + 8 * (HH * DD);
    #pragma unroll
    for (int nt = 0; nt < 8; nt++) {
        *(float2*)&o0[nt * 8 + 2 * t] = make_float2(oC[nt][0] * inv0, oC[nt][1] * inv0);
        *(float2*)&o1[nt * 8 + 2 * t] = make_float2(oC[nt][2] * inv1, oC[nt][3] * inv1);
    }
}

// ---------------- host launcher ------------------------------------------------
extern "C" void kernel_launch(void* const* d_in, const int* in_sizes, int n_in,
                              void* d_out, int out_size) {
    const float* x        = (const float*)d_in[0];
    const float* c_emb    = (const float*)d_in[1];
    const float* ln_g     = (const float*)d_in[2];
    const float* ln_b     = (const float*)d_in[3];
    const float* ctx_ln_g = (const float*)d_in[4];
    const float* ctx_ln_b = (const float*)d_in[5];
    const float* W_ctx    = (const float*)d_in[6];
    const float* b_ctx    = (const float*)d_in[7];
    const float* W_q      = (const float*)d_in[8];
    const float* W_kv     = (const float*)d_in[9];
    const float* null_kv  = (const float*)d_in[10];
    const float* W_out    = (const float*)d_in[11];
    const float* out_ln_g = (const float*)d_in[12];
    const float* out_ln_b = (const float*)d_in[13];
    float* out = (float*)d_out;

    float *xn, *qb, *kext, *vext, *kt, *vt, *attn, *proj;
    cudaGetSymbolAddress((void**)&xn,   g_xn);
    cudaGetSymbolAddress((void**)&qb,   g_q);
    cudaGetSymbolAddress((void**)&kext, g_kext);
    cudaGetSymbolAddress((void**)&vext, g_vext);
    cudaGetSymbolAddress((void**)&kt,   g_kt);
    cudaGetSymbolAddress((void**)&vt,   g_vt);
    cudaGetSymbolAddress((void**)&attn, g_attn);
    cudaGetSymbolAddress((void**)&proj, g_proj);

    const int smem1 = 2 * (1 * ATILE + BTILE) * 4;   // 37888 B
    const int smem2 = 2 * (2 * ATILE + BTILE) * 4;   // 58368 B
    const int smemA = 256 * SPITCH * 4;              // 69632 B (K+V+P)
    cudaFuncSetAttribute((const void*)mma_gemm<1,0>, cudaFuncAttributeMaxDynamicSharedMemorySize, smem1);
    cudaFuncSetAttribute((const void*)mma_gemm<1,1>, cudaFuncAttributeMaxDynamicSharedMemorySize, smem1);
    cudaFuncSetAttribute((const void*)mma_gemm<2,0>, cudaFuncAttributeMaxDynamicSharedMemorySize, smem2);
    cudaFuncSetAttribute((const void*)attn_mma_kernel, cudaFuncAttributeMaxDynamicSharedMemorySize, smemA);

    ln_kernel<<<ROWS, 256>>>(x, xn, ln_g, ln_b, IND);
    ctx_kernel<<<BB * MM, 256>>>(c_emb, ctx_ln_g, ctx_ln_b, W_ctx, b_ctx, kext, vext);
    null_kernel<<<1, 128>>>(null_kv, kext, vext);
    pack_ext_kernel<<<BB * HH, 256>>>(kext, vext, kt, vt);
    // Q projection
    mma_gemm<1,0><<<dim3((HH * DD) / 128, ROWS / 128), 256, smem1>>>(
        xn, W_q, qb, ROWS, HH * DD, IND, nullptr, nullptr);
    // KV projection with fused pack epilogue (writes kt / vt directly)
    mma_gemm<1,1><<<dim3(KVW / 128, ROWS / 128), 256, smem1>>>(
        xn, W_kv, nullptr, ROWS, KVW, IND, kt, vt);
    // attention (8 warps / 128 q-rows per CTA)
    attn_mma_kernel<<<dim3(NN / 128, HH, BB), 256, smemA>>>(qb, kt, vt, attn);
    // output projection (split-A for accuracy)
    mma_gemm<2,0><<<dim3(IND / 128, ROWS / 128), 256, smem2>>>(
        attn, W_out, proj, ROWS, IND, IND, nullptr, nullptr);
    ln_kernel<<<ROWS, 256>>>(proj, out, out_ln_g, out_ln_b, IND);
}

// round 12
// speedup vs baseline: 1.1094x; 1.0359x over previous
#include <cuda_runtime.h>
#include <cuda_bf16.h>
#include <math.h>

// Problem constants
#define BB   2
#define NN   2048
#define MM   128
#define HH   16
#define DD   64
#define IND  1024
#define CTXD 768
#define ROWS (BB*NN)          // 4096
#define KVW  (2*HH*DD)        // 2048
#define KEXT 129              // 1 null + 128 ctx keys

// attention tiling
#define NKEYS  2240           // 2048 self + 129 ext, padded to 35*64
#define NTILES 35
#define LIMIT  2177
#define SPITCH 68

// mma gemm tiling (R6-proven: 8 warps, 64x32 warp tiles, 256 threads)
#define APITCH 20             // floats; (20g+t)%32 distinct -> conflict-free A frags
#define BPITCH 136            // floats; (8t+g)%32 distinct -> conflict-free B frags
#define ATILE  (128*APITCH)   // floats per A tile
#define BTILE  (16*BPITCH)    // floats per B tile

// ---------------- scratch (static device globals; no allocation) -------------
__device__ float g_xn  [ROWS*IND];
__device__ float g_q   [ROWS*HH*DD];
__device__ float g_kext[BB*KEXT*DD];
__device__ float g_vext[BB*KEXT*DD];
__device__ float g_kt  [BB*HH*NKEYS*DD];   // K packed  [b][h][key][d]  (tf32 bits)
__device__ float g_vt  [BB*HH*DD*NKEYS];   // V^T packed [b][h][d][key] (tf32 bits)
__device__ float g_attn[ROWS*HH*DD];
__device__ float g_proj[ROWS*IND];

// ---------------- tf32 helpers -------------------------------------------------
__device__ __forceinline__ unsigned f2tf32(float x) {
    unsigned r; asm("cvt.rna.tf32.f32 %0, %1;" : "=r"(r) : "f"(x)); return r;
}
__device__ __forceinline__ float tf32f(float x) {
    return __uint_as_float(f2tf32(x));
}

#define MMA_TF32(c, a, b0_, b1_)                                               \
    asm volatile("mma.sync.aligned.m16n8k8.row.col.f32.tf32.tf32.f32 "         \
                 "{%0,%1,%2,%3}, {%4,%5,%6,%7}, {%8,%9}, {%0,%1,%2,%3};"       \
                 : "+f"((c)[0]), "+f"((c)[1]), "+f"((c)[2]), "+f"((c)[3])      \
                 : "r"((a)[0]), "r"((a)[1]), "r"((a)[2]), "r"((a)[3]),         \
                   "r"(b0_), "r"(b1_))

// ---------------- block reduction helper -------------------------------------
__device__ __forceinline__ float block_reduce_sum(float v, float* sbuf) {
    __syncthreads();
    int lane = threadIdx.x & 31, warp = threadIdx.x >> 5;
    #pragma unroll
    for (int o = 16; o; o >>= 1) v += __shfl_xor_sync(0xffffffffu, v, o);
    if (lane == 0) sbuf[warp] = v;
    __syncthreads();
    int nw = (blockDim.x + 31) >> 5;
    v = (threadIdx.x < nw) ? sbuf[threadIdx.x] : 0.0f;
    if (warp == 0) {
        #pragma unroll
        for (int o = 16; o; o >>= 1) v += __shfl_xor_sync(0xffffffffu, v, o);
        if (lane == 0) sbuf[0] = v;
    }
    __syncthreads();
    return sbuf[0];
}

// ---------------- layernorm (one block per row) -------------------------------
__global__ void ln_kernel(const float* __restrict__ in, float* __restrict__ out,
                          const float* __restrict__ g, const float* __restrict__ b,
                          int C) {
    __shared__ float sbuf[32];
    const float* x = in + (size_t)blockIdx.x * C;
    float s = 0.f, s2 = 0.f;
    for (int i = threadIdx.x; i < C; i += blockDim.x) {
        float v = x[i]; s += v; s2 += v * v;
    }
    s  = block_reduce_sum(s,  sbuf);
    s2 = block_reduce_sum(s2, sbuf);
    float mean = s / C;
    float rstd = rsqrtf(s2 / C - mean * mean + 1e-5f);
    float* o = out + (size_t)blockIdx.x * C;
    for (int i = threadIdx.x; i < C; i += blockDim.x)
        o[i] = (x[i] - mean) * rstd * g[i] + b[i];
}

// ---------------- ctx branch: LN(768) + GEMV(768x128) fused --------------------
__global__ void ctx_kernel(const float* __restrict__ c_emb,
                           const float* __restrict__ g, const float* __restrict__ b,
                           const float* __restrict__ W,
                           const float* __restrict__ bctx,
                           float* __restrict__ kext, float* __restrict__ vext) {
    __shared__ float row[CTXD];
    __shared__ float sbuf[32];
    int rid = blockIdx.x;
    int bb = rid >> 7, m = rid & 127;
    const float* x = c_emb + (size_t)rid * CTXD;
    float s = 0.f, s2 = 0.f;
    for (int i = threadIdx.x; i < CTXD; i += blockDim.x) {
        float v = x[i]; row[i] = v; s += v; s2 += v * v;
    }
    s  = block_reduce_sum(s,  sbuf);
    s2 = block_reduce_sum(s2, sbuf);
    float mean = s / CTXD;
    float rstd = rsqrtf(s2 / CTXD - mean * mean + 1e-5f);
    for (int i = threadIdx.x; i < CTXD; i += blockDim.x)
        row[i] = (row[i] - mean) * rstd * g[i] + b[i];
    __syncthreads();
    if (threadIdx.x < 128) {
        int j = threadIdx.x;
        float acc = bctx[j];
        #pragma unroll 8
        for (int d = 0; d < CTXD; d++) acc += row[d] * W[d * 128 + j];
        if (j < DD) kext[((size_t)bb * KEXT + m + 1) * DD + j] = acc;
        else        vext[((size_t)bb * KEXT + m + 1) * DD + (j - DD)] = acc;
    }
}

// ---------------- write null K/V rows -----------------------------------------
__global__ void null_kernel(const float* __restrict__ null_kv,
                            float* __restrict__ kext, float* __restrict__ vext) {
    int t = threadIdx.x;
    if (t < DD) {
        float v = null_kv[t];
        kext[0 * KEXT * DD + t] = v;
        kext[1 * KEXT * DD + t] = v;
    } else {
        int d = t - DD;
        float v = null_kv[DD + d];
        vext[0 * KEXT * DD + d] = v;
        vext[1 * KEXT * DD + d] = v;
    }
}

// ---------------- pack EXT region (keys 2048..2239) into Kp / Vt ---------------
// Flattened: grid 1536 x 256 threads, one element per thread (fully parallel).
__global__ void pack_ext_kernel(const float* __restrict__ kext,
                                const float* __restrict__ vext,
                                float* __restrict__ Kp, float* __restrict__ Vt) {
    const int NE = NKEYS - NN;            // 192 ext+pad keys
    int idx = blockIdx.x * 256 + threadIdx.x;   // 0 .. 32*192*64-1
    int d  = idx & 63;
    int kl = (idx >> 6) % NE;
    int bh = idx / (NE * 64);
    int b = bh >> 4;
    int key = NN + kl;
    float kvval = 0.f, vvval = 0.f;
    if (key < LIMIT) {
        size_t off = ((size_t)b * KEXT + kl) * DD + d;
        kvval = tf32f(kext[off]);
        vvval = tf32f(vext[off]);
    }
    Kp[((size_t)bh * NKEYS + key) * DD + d] = kvval;
    Vt[((size_t)bh * DD + d) * NKEYS + key] = vvval;
}

// ---------------- tf32 mma GEMM: C = A(MxK) x B(KxN), row-major -----------------
// R6-proven config: 128x128 CTA tile, BK=16, 8 warps (2x4), warp tile 64x32.
// SPLITA=1: plain tf32. SPLITA=2: A split hi/lo (2 passes) for higher accuracy.
// MODE=0: write C.  MODE=1: KV-pack epilogue -> write Kp (k half) / Vt (v half)
// with tf32 rounding; C not written.
template<int SPLITA, int MODE>
__global__ __launch_bounds__(256) void mma_gemm(
        const float* __restrict__ A, const float* __restrict__ B,
        float* __restrict__ C, int M, int N, int K,
        float* __restrict__ Kp, float* __restrict__ Vt) {
    extern __shared__ float smf[];
    const int PER = SPLITA * ATILE + BTILE;

    int tid = threadIdx.x;
    int w = tid >> 5, lane = tid & 31, g = lane >> 2, t = lane & 3;
    int wm = (w >> 2) * 64, wn = (w & 3) * 32;

    const float* Ab = A + (size_t)(blockIdx.y * 128) * K;
    const float* Bb = B + (size_t)(blockIdx.x * 128);

    int aRow = tid >> 1,  aCol = (tid & 1) * 8;
    int bRow = tid >> 4,  bCol = (tid & 15) * 8;

    float acc[4][4][4];
    #pragma unroll
    for (int mi = 0; mi < 4; mi++)
        #pragma unroll
        for (int nj = 0; nj < 4; nj++)
            #pragma unroll
            for (int q = 0; q < 4; q++) acc[mi][nj][q] = 0.f;

    float4 pa0, pa1, pb0, pb1;
    {
        const float* ap = Ab + (size_t)aRow * K + aCol;
        pa0 = *(const float4*)ap; pa1 = *(const float4*)(ap + 4);
        const float* bp = Bb + (size_t)bRow * N + bCol;
        pb0 = *(const float4*)bp; pb1 = *(const float4*)(bp + 4);
    }
    // store tile 0
    {
        float* base = smf;
        float* AhP = base;
        float* BhP = base + SPLITA * ATILE;
        float4 h0 = make_float4(tf32f(pa0.x), tf32f(pa0.y), tf32f(pa0.z), tf32f(pa0.w));
        float4 h1 = make_float4(tf32f(pa1.x), tf32f(pa1.y), tf32f(pa1.z), tf32f(pa1.w));
        *(float4*)&AhP[aRow * APITCH + aCol]     = h0;
        *(float4*)&AhP[aRow * APITCH + aCol + 4] = h1;
        if (SPLITA == 2) {
            float* AlP = base + ATILE;
            *(float4*)&AlP[aRow * APITCH + aCol] =
                make_float4(tf32f(pa0.x - h0.x), tf32f(pa0.y - h0.y), tf32f(pa0.z - h0.z), tf32f(pa0.w - h0.w));
            *(float4*)&AlP[aRow * APITCH + aCol + 4] =
                make_float4(tf32f(pa1.x - h1.x), tf32f(pa1.y - h1.y), tf32f(pa1.z - h1.z), tf32f(pa1.w - h1.w));
        }
        *(float4*)&BhP[bRow * BPITCH + bCol] =
            make_float4(tf32f(pb0.x), tf32f(pb0.y), tf32f(pb0.z), tf32f(pb0.w));
        *(float4*)&BhP[bRow * BPITCH + bCol + 4] =
            make_float4(tf32f(pb1.x), tf32f(pb1.y), tf32f(pb1.z), tf32f(pb1.w));
    }
    __syncthreads();

    int buf = 0;
    for (int k0 = 0; k0 < K; k0 += 16) {
        bool next = (k0 + 16) < K;
        if (next) {
            const float* ap = Ab + (size_t)aRow * K + (k0 + 16) + aCol;
            pa0 = *(const float4*)ap; pa1 = *(const float4*)(ap + 4);
            const float* bp = Bb + (size_t)(k0 + 16 + bRow) * N + bCol;
            pb0 = *(const float4*)bp; pb1 = *(const float4*)(bp + 4);
        }
        float* base = smf + buf * PER;
        const float* AhP = base;
        const float* AlP = base + ATILE;
        const float* BhP = base + SPLITA * ATILE;
        #pragma unroll
        for (int kk = 0; kk < 2; kk++) {
            int k = kk * 8;
            unsigned aF[4][4], bF[4][2];
            #pragma unroll
            for (int mi = 0; mi < 4; mi++) {
                const float* ap2 = AhP + (wm + mi * 16 + g) * APITCH + k + t;
                aF[mi][0] = __float_as_uint(ap2[0]);
                aF[mi][1] = __float_as_uint(ap2[8 * APITCH]);
                aF[mi][2] = __float_as_uint(ap2[4]);
                aF[mi][3] = __float_as_uint(ap2[8 * APITCH + 4]);
            }
            #pragma unroll
            for (int nj = 0; nj < 4; nj++) {
                const float* bp2 = BhP + (k + t) * BPITCH + wn + nj * 8 + g;
                bF[nj][0] = __float_as_uint(bp2[0]);
                bF[nj][1] = __float_as_uint(bp2[4 * BPITCH]);
            }
            #pragma unroll
            for (int mi = 0; mi < 4; mi++)
                #pragma unroll
                for (int nj = 0; nj < 4; nj++)
                    MMA_TF32(acc[mi][nj], aF[mi], bF[nj][0], bF[nj][1]);
            if (SPLITA == 2) {
                unsigned aL[4][4];
                #pragma unroll
                for (int mi = 0; mi < 4; mi++) {
                    const float* ap2 = AlP + (wm + mi * 16 + g) * APITCH + k + t;
                    aL[mi][0] = __float_as_uint(ap2[0]);
                    aL[mi][1] = __float_as_uint(ap2[8 * APITCH]);
                    aL[mi][2] = __float_as_uint(ap2[4]);
                    aL[mi][3] = __float_as_uint(ap2[8 * APITCH + 4]);
                }
                #pragma unroll
                for (int mi = 0; mi < 4; mi++)
                    #pragma unroll
                    for (int nj = 0; nj < 4; nj++)
                        MMA_TF32(acc[mi][nj], aL[mi], bF[nj][0], bF[nj][1]);
            }
        }
        if (next) {
            float* nb = smf + (buf ^ 1) * PER;
            float* AhP2 = nb;
            float* BhP2 = nb + SPLITA * ATILE;
            float4 h0 = make_float4(tf32f(pa0.x), tf32f(pa0.y), tf32f(pa0.z), tf32f(pa0.w));
            float4 h1 = make_float4(tf32f(pa1.x), tf32f(pa1.y), tf32f(pa1.z), tf32f(pa1.w));
            *(float4*)&AhP2[aRow * APITCH + aCol]     = h0;
            *(float4*)&AhP2[aRow * APITCH + aCol + 4] = h1;
            if (SPLITA == 2) {
                float* AlP2 = nb + ATILE;
                *(float4*)&AlP2[aRow * APITCH + aCol] =
                    make_float4(tf32f(pa0.x - h0.x), tf32f(pa0.y - h0.y), tf32f(pa0.z - h0.z), tf32f(pa0.w - h0.w));
                *(float4*)&AlP2[aRow * APITCH + aCol + 4] =
                    make_float4(tf32f(pa1.x - h1.x), tf32f(pa1.y - h1.y), tf32f(pa1.z - h1.z), tf32f(pa1.w - h1.w));
            }
            *(float4*)&BhP2[bRow * BPITCH + bCol] =
                make_float4(tf32f(pb0.x), tf32f(pb0.y), tf32f(pb0.z), tf32f(pb0.w));
            *(float4*)&BhP2[bRow * BPITCH + bCol + 4] =
                make_float4(tf32f(pb1.x), tf32f(pb1.y), tf32f(pb1.z), tf32f(pb1.w));
            __syncthreads();
            buf ^= 1;
        }
    }

    if (MODE == 0) {
        #pragma unroll
        for (int mi = 0; mi < 4; mi++) {
            int row = blockIdx.y * 128 + wm + mi * 16 + g;
            #pragma unroll
            for (int nj = 0; nj < 4; nj++) {
                int col = blockIdx.x * 128 + wn + nj * 8 + 2 * t;
                *(float2*)&C[(size_t)row * N + col]       = make_float2(acc[mi][nj][0], acc[mi][nj][1]);
                *(float2*)&C[(size_t)(row + 8) * N + col] = make_float2(acc[mi][nj][2], acc[mi][nj][3]);
            }
        }
    } else {
        // KV pack epilogue: row = token, col -> (s, h, d); write Kp / Vt (tf32).
        #pragma unroll
        for (int mi = 0; mi < 4; mi++) {
            int row = blockIdx.y * 128 + wm + mi * 16 + g;
            #pragma unroll
            for (int nj = 0; nj < 4; nj++) {
                int col = blockIdx.x * 128 + wn + nj * 8 + 2 * t;
                int s = col >> 10, h = (col >> 6) & 15, d = col & 63;
                #pragma unroll
                for (int half = 0; half < 2; half++) {
                    int tok = row + half * 8;
                    int b = tok >> 11, n = tok & 2047;
                    int bh = b * HH + h;
                    float v0 = tf32f(acc[mi][nj][half * 2 + 0]);
                    float v1 = tf32f(acc[mi][nj][half * 2 + 1]);
                    if (s == 0) {
                        *(float2*)&Kp[((size_t)bh * NKEYS + n) * DD + d] = make_float2(v0, v1);
                    } else {
                        Vt[((size_t)bh * DD + d)     * NKEYS + n] = v0;
                        Vt[((size_t)bh * DD + d + 1) * NKEYS + n] = v1;
                    }
                }
            }
        }
    }
}

// ---------------- flash attention on tensor cores (tf32 mma.sync) --------------
// R6-proven: grid (N/64, H, B), 128 threads = 4 warps; 64-key tiles; P reuses Ksm.
__global__ __launch_bounds__(128) void attn_mma_kernel(
        const float* __restrict__ qb,
        const float* __restrict__ Kp,
        const float* __restrict__ Vt,
        float* __restrict__ outb) {
    __shared__ float Ksm[64 * SPITCH];
    __shared__ float Vsm[64 * SPITCH];
    int b = blockIdx.z, h = blockIdx.y;
    int tid = threadIdx.x;
    int w = tid >> 5, lane = tid & 31;
    int g = lane >> 2, t = lane & 3;
    int qa = blockIdx.x * 64 + w * 16 + g;

    unsigned qA[8][4];
    {
        const float* q0 = qb + ((size_t)(b * NN + qa)) * (HH * DD) + h * DD;
        const float* q1 = q0 + 8 * (HH * DD);
        #pragma unroll
        for (int kk = 0; kk < 8; kk++) {
            qA[kk][0] = f2tf32(q0[kk * 8 + t]     * 0.125f);
            qA[kk][1] = f2tf32(q1[kk * 8 + t]     * 0.125f);
            qA[kk][2] = f2tf32(q0[kk * 8 + t + 4] * 0.125f);
            qA[kk][3] = f2tf32(q1[kk * 8 + t + 4] * 0.125f);
        }
    }

    const float* Kg = Kp + ((size_t)(b * HH + h)) * NKEYS * DD;
    const float* Vg = Vt + ((size_t)(b * HH + h)) * DD * NKEYS;

    float m0 = -1e30f, m1 = -1e30f, l0 = 0.f, l1 = 0.f;
    float oC[8][4];
    #pragma unroll
    for (int nt = 0; nt < 8; nt++)
        #pragma unroll
        for (int j = 0; j < 4; j++) oC[nt][j] = 0.f;

    float* Prow0 = &Ksm[(w * 16 + g)     * SPITCH];
    float* Prow1 = &Ksm[(w * 16 + g + 8) * SPITCH];

    for (int tile = 0; tile < NTILES; tile++) {
        int tb = tile * 64;
        __syncthreads();
        #pragma unroll
        for (int i = 0; i < 8; i++) {
            int idx = tid + i * 128;
            int r = idx >> 4, c = (idx & 15) * 4;
            *(float4*)&Ksm[r * SPITCH + c] = *(const float4*)&Kg[(size_t)(tb + r) * DD + c];
            *(float4*)&Vsm[r * SPITCH + c] = *(const float4*)&Vg[(size_t)r * NKEYS + tb + c];
        }
        __syncthreads();

        float sC[8][4];
        #pragma unroll
        for (int nt = 0; nt < 8; nt++)
            #pragma unroll
            for (int j = 0; j < 4; j++) sC[nt][j] = 0.f;
        #pragma unroll
        for (int kk = 0; kk < 8; kk++) {
            #pragma unroll
            for (int nt = 0; nt < 8; nt++) {
                const float* kr = &Ksm[(nt * 8 + g) * SPITCH + kk * 8 + t];
                unsigned b0 = __float_as_uint(kr[0]);
                unsigned b1 = __float_as_uint(kr[4]);
                MMA_TF32(sC[nt], qA[kk], b0, b1);
            }
        }

        int lim = LIMIT - tb;
        float tmax0 = -1e30f, tmax1 = -1e30f;
        #pragma unroll
        for (int nt = 0; nt < 8; nt++) {
            int c0 = nt * 8 + 2 * t, c1 = c0 + 1;
            if (c0 >= lim) { sC[nt][0] = -1e30f; sC[nt][2] = -1e30f; }
            if (c1 >= lim) { sC[nt][1] = -1e30f; sC[nt][3] = -1e30f; }
            tmax0 = fmaxf(tmax0, fmaxf(sC[nt][0], sC[nt][1]));
            tmax1 = fmaxf(tmax1, fmaxf(sC[nt][2], sC[nt][3]));
        }
        tmax0 = fmaxf(tmax0, __shfl_xor_sync(0xffffffffu, tmax0, 1));
        tmax0 = fmaxf(tmax0, __shfl_xor_sync(0xffffffffu, tmax0, 2));
        tmax1 = fmaxf(tmax1, __shfl_xor_sync(0xffffffffu, tmax1, 1));
        tmax1 = fmaxf(tmax1, __shfl_xor_sync(0xffffffffu, tmax1, 2));

        float mn0 = fmaxf(m0, tmax0), mn1 = fmaxf(m1, tmax1);
        float corr0 = __expf(m0 - mn0), corr1 = __expf(m1 - mn1);
        m0 = mn0; m1 = mn1;

        __syncthreads();
        float ps0 = 0.f, ps1 = 0.f;
        #pragma unroll
        for (int nt = 0; nt < 8; nt++) {
            float p0 = __expf(sC[nt][0] - m0), p1 = __expf(sC[nt][1] - m0);
            float p2 = __expf(sC[nt][2] - m1), p3 = __expf(sC[nt][3] - m1);
            ps0 += p0 + p1; ps1 += p2 + p3;
            *(float2*)&Prow0[nt * 8 + 2 * t] = make_float2(tf32f(p0), tf32f(p1));
            *(float2*)&Prow1[nt * 8 + 2 * t] = make_float2(tf32f(p2), tf32f(p3));
            oC[nt][0] *= corr0; oC[nt][1] *= corr0;
            oC[nt][2] *= corr1; oC[nt][3] *= corr1;
        }
        l0 = l0 * corr0 + ps0;
        l1 = l1 * corr1 + ps1;
        __syncwarp();

        #pragma unroll
        for (int kk = 0; kk < 8; kk++) {
            unsigned a[4];
            a[0] = __float_as_uint(Prow0[kk * 8 + t]);
            a[1] = __float_as_uint(Prow1[kk * 8 + t]);
            a[2] = __float_as_uint(Prow0[kk * 8 + t + 4]);
            a[3] = __float_as_uint(Prow1[kk * 8 + t + 4]);
            #pragma unroll
            for (int nd = 0; nd < 8; nd++) {
                const float* vr = &Vsm[(nd * 8 + g) * SPITCH + kk * 8 + t];
                unsigned b0 = __float_as_uint(vr[0]);
                unsigned b1 = __float_as_uint(vr[4]);
                MMA_TF32(oC[nd], a, b0, b1);
            }
        }
    }

    l0 += __shfl_xor_sync(0xffffffffu, l0, 1);
    l0 += __shfl_xor_sync(0xffffffffu, l0, 2);
    l1 += __shfl_xor_sync(0xffffffffu, l1, 1);
    l1 += __shfl_xor_sync(0xffffffffu, l1, 2);
    float inv0 = 1.f / l0, inv1 = 1.f / l1;
    float* o0 = outb + ((size_t)(b * NN + qa)) * (HH * DD) + h * DD;
    float* o1 = o0 + 8 * (HH * DD);
    #pragma unroll
    for (int nt = 0; nt < 8; nt++) {
        *(float2*)&o0[nt * 8 + 2 * t] = make_float2(oC[nt][0] * inv0, oC[nt][1] * inv0);
        *(float2*)&o1[nt * 8 + 2 * t] = make_float2(oC[nt][2] * inv1, oC[nt][3] * inv1);
    }
}

// ---------------- host launcher ------------------------------------------------
extern "C" void kernel_launch(void* const* d_in, const int* in_sizes, int n_in,
                              void* d_out, int out_size) {
    const float* x        = (const float*)d_in[0];
    const float* c_emb    = (const float*)d_in[1];
    const float* ln_g     = (const float*)d_in[2];
    const float* ln_b     = (const float*)d_in[3];
    const float* ctx_ln_g = (const float*)d_in[4];
    const float* ctx_ln_b = (const float*)d_in[5];
    const float* W_ctx    = (const float*)d_in[6];
    const float* b_ctx    = (const float*)d_in[7];
    const float* W_q      = (const float*)d_in[8];
    const float* W_kv     = (const float*)d_in[9];
    const float* null_kv  = (const float*)d_in[10];
    const float* W_out    = (const float*)d_in[11];
    const float* out_ln_g = (const float*)d_in[12];
    const float* out_ln_b = (const float*)d_in[13];
    float* out = (float*)d_out;

    float *xn, *qb, *kext, *vext, *kt, *vt, *attn, *proj;
    cudaGetSymbolAddress((void**)&xn,   g_xn);
    cudaGetSymbolAddress((void**)&qb,   g_q);
    cudaGetSymbolAddress((void**)&kext, g_kext);
    cudaGetSymbolAddress((void**)&vext, g_vext);
    cudaGetSymbolAddress((void**)&kt,   g_kt);
    cudaGetSymbolAddress((void**)&vt,   g_vt);
    cudaGetSymbolAddress((void**)&attn, g_attn);
    cudaGetSymbolAddress((void**)&proj, g_proj);

    const int smem1 = 2 * (1 * ATILE + BTILE) * 4;   // 37888 B
    const int smem2 = 2 * (2 * ATILE + BTILE) * 4;   // 58368 B
    cudaFuncSetAttribute((const void*)mma_gemm<1,0>, cudaFuncAttributeMaxDynamicSharedMemorySize, smem1);
    cudaFuncSetAttribute((const void*)mma_gemm<1,1>, cudaFuncAttributeMaxDynamicSharedMemorySize, smem1);
    cudaFuncSetAttribute((const void*)mma_gemm<2,0>, cudaFuncAttributeMaxDynamicSharedMemorySize, smem2);

    ln_kernel<<<ROWS, 256>>>(x, xn, ln_g, ln_b, IND);
    ctx_kernel<<<BB * MM, 256>>>(c_emb, ctx_ln_g, ctx_ln_b, W_ctx, b_ctx, kext, vext);
    null_kernel<<<1, 128>>>(null_kv, kext, vext);
    pack_ext_kernel<<<(BB * HH * (NKEYS - NN) * DD) / 256, 256>>>(kext, vext, kt, vt);
    // Q projection
    mma_gemm<1,0><<<dim3((HH * DD) / 128, ROWS / 128), 256, smem1>>>(
        xn, W_q, qb, ROWS, HH * DD, IND, nullptr, nullptr);
    // KV projection with fused pack epilogue (writes kt / vt directly)
    mma_gemm<1,1><<<dim3(KVW / 128, ROWS / 128), 256, smem1>>>(
        xn, W_kv, nullptr, ROWS, KVW, IND, kt, vt);
    // attention (R6-proven 4-warp version)
    attn_mma_kernel<<<dim3(NN / 64, HH, BB), 128>>>(qb, kt, vt, attn);
    // output projection (split-A for accuracy)
    mma_gemm<2,0><<<dim3(IND / 128, ROWS / 128), 256, smem2>>>(
        attn, W_out, proj, ROWS, IND, IND, nullptr, nullptr);
    ln_kernel<<<ROWS, 256>>>(proj, out, out_ln_g, out_ln_b, IND);
}

// round 13
// speedup vs baseline: 1.1499x; 1.0365x over previous
#include <cuda_runtime.h>
#include <cuda_bf16.h>
#include <math.h>

// Problem constants
#define BB   2
#define NN   2048
#define MM   128
#define HH   16
#define DD   64
#define IND  1024
#define CTXD 768
#define ROWS (BB*NN)          // 4096
#define KVW  (2*HH*DD)        // 2048
#define KEXT 129              // 1 null + 128 ctx keys

// attention tiling
#define NKEYS  2240           // 2048 self + 129 ext, padded to 35*64
#define NTILES 35
#define LIMIT  2177
#define SPITCH 68

// mma gemm tiling (R6-proven: 8 warps, 64x32 warp tiles, 256 threads)
#define APITCH 20             // floats; (20g+t)%32 distinct -> conflict-free A frags
#define BPITCH 136            // floats; (8t+g)%32 distinct -> conflict-free B frags
#define ATILE  (128*APITCH)   // floats per A tile
#define BTILE  (16*BPITCH)    // floats per B tile

// ---------------- scratch (static device globals; no allocation) -------------
__device__ float g_xn  [ROWS*IND];
__device__ float g_q   [ROWS*HH*DD];
__device__ float g_kext[BB*KEXT*DD];
__device__ float g_vext[BB*KEXT*DD];
__device__ float g_kt  [BB*HH*NKEYS*DD];   // K packed  [b][h][key][d]  (tf32 bits)
__device__ float g_vt  [BB*HH*DD*NKEYS];   // V^T packed [b][h][d][key] (tf32 bits)
__device__ float g_attn[ROWS*HH*DD];
__device__ float g_proj[ROWS*IND];

// ---------------- tf32 helpers -------------------------------------------------
__device__ __forceinline__ unsigned f2tf32(float x) {
    unsigned r; asm("cvt.rna.tf32.f32 %0, %1;" : "=r"(r) : "f"(x)); return r;
}
__device__ __forceinline__ float tf32f(float x) {
    return __uint_as_float(f2tf32(x));
}

#define MMA_TF32(c, a, b0_, b1_)                                               \
    asm volatile("mma.sync.aligned.m16n8k8.row.col.f32.tf32.tf32.f32 "         \
                 "{%0,%1,%2,%3}, {%4,%5,%6,%7}, {%8,%9}, {%0,%1,%2,%3};"       \
                 : "+f"((c)[0]), "+f"((c)[1]), "+f"((c)[2]), "+f"((c)[3])      \
                 : "r"((a)[0]), "r"((a)[1]), "r"((a)[2]), "r"((a)[3]),         \
                   "r"(b0_), "r"(b1_))

// ---------------- block reduction helper -------------------------------------
__device__ __forceinline__ float block_reduce_sum(float v, float* sbuf) {
    __syncthreads();
    int lane = threadIdx.x & 31, warp = threadIdx.x >> 5;
    #pragma unroll
    for (int o = 16; o; o >>= 1) v += __shfl_xor_sync(0xffffffffu, v, o);
    if (lane == 0) sbuf[warp] = v;
    __syncthreads();
    int nw = (blockDim.x + 31) >> 5;
    v = (threadIdx.x < nw) ? sbuf[threadIdx.x] : 0.0f;
    if (warp == 0) {
        #pragma unroll
        for (int o = 16; o; o >>= 1) v += __shfl_xor_sync(0xffffffffu, v, o);
        if (lane == 0) sbuf[0] = v;
    }
    __syncthreads();
    return sbuf[0];
}

// ---------------- layernorm (one block per row) -------------------------------
__global__ void ln_kernel(const float* __restrict__ in, float* __restrict__ out,
                          const float* __restrict__ g, const float* __restrict__ b,
                          int C) {
    __shared__ float sbuf[32];
    const float* x = in + (size_t)blockIdx.x * C;
    float s = 0.f, s2 = 0.f;
    for (int i = threadIdx.x; i < C; i += blockDim.x) {
        float v = x[i]; s += v; s2 += v * v;
    }
    s  = block_reduce_sum(s,  sbuf);
    s2 = block_reduce_sum(s2, sbuf);
    float mean = s / C;
    float rstd = rsqrtf(s2 / C - mean * mean + 1e-5f);
    float* o = out + (size_t)blockIdx.x * C;
    for (int i = threadIdx.x; i < C; i += blockDim.x)
        o[i] = (x[i] - mean) * rstd * g[i] + b[i];
}

// ---------------- ctx branch: LN(768) + GEMV(768x128) fused --------------------
__global__ void ctx_kernel(const float* __restrict__ c_emb,
                           const float* __restrict__ g, const float* __restrict__ b,
                           const float* __restrict__ W,
                           const float* __restrict__ bctx,
                           float* __restrict__ kext, float* __restrict__ vext) {
    __shared__ float row[CTXD];
    __shared__ float sbuf[32];
    int rid = blockIdx.x;
    int bb = rid >> 7, m = rid & 127;
    const float* x = c_emb + (size_t)rid * CTXD;
    float s = 0.f, s2 = 0.f;
    for (int i = threadIdx.x; i < CTXD; i += blockDim.x) {
        float v = x[i]; row[i] = v; s += v; s2 += v * v;
    }
    s  = block_reduce_sum(s,  sbuf);
    s2 = block_reduce_sum(s2, sbuf);
    float mean = s / CTXD;
    float rstd = rsqrtf(s2 / CTXD - mean * mean + 1e-5f);
    for (int i = threadIdx.x; i < CTXD; i += blockDim.x)
        row[i] = (row[i] - mean) * rstd * g[i] + b[i];
    __syncthreads();
    if (threadIdx.x < 128) {
        int j = threadIdx.x;
        float acc = bctx[j];
        #pragma unroll 8
        for (int d = 0; d < CTXD; d++) acc += row[d] * W[d * 128 + j];
        if (j < DD) kext[((size_t)bb * KEXT + m + 1) * DD + j] = acc;
        else        vext[((size_t)bb * KEXT + m + 1) * DD + (j - DD)] = acc;
    }
}

// ---------------- pack EXT region (keys 2048..2239) into Kp / Vt ---------------
// Flattened: grid 1536 x 256 threads, one element per thread. Null row (key 2048)
// is read straight from null_kv (null_kernel folded in).
__global__ void pack_ext_kernel(const float* __restrict__ kext,
                                const float* __restrict__ vext,
                                const float* __restrict__ null_kv,
                                float* __restrict__ Kp, float* __restrict__ Vt) {
    const int NE = NKEYS - NN;            // 192 ext+pad keys
    int idx = blockIdx.x * 256 + threadIdx.x;   // 0 .. 32*192*64-1
    int d  = idx & 63;
    int kl = (idx >> 6) % NE;
    int bh = idx / (NE * 64);
    int b = bh >> 4;
    int key = NN + kl;
    float kvval = 0.f, vvval = 0.f;
    if (kl == 0) {
        kvval = tf32f(null_kv[d]);
        vvval = tf32f(null_kv[DD + d]);
    } else if (key < LIMIT) {
        size_t off = ((size_t)b * KEXT + kl) * DD + d;
        kvval = tf32f(kext[off]);
        vvval = tf32f(vext[off]);
    }
    Kp[((size_t)bh * NKEYS + key) * DD + d] = kvval;
    Vt[((size_t)bh * DD + d) * NKEYS + key] = vvval;
}

// ---------------- tf32 mma GEMM: C = A(MxK) x B(KxN), row-major -----------------
// R6-proven config: 128x128 CTA tile, BK=16, 8 warps (2x4), warp tile 64x32.
// SPLITA=1: plain tf32. SPLITA=2: A split hi/lo (2 passes) for higher accuracy.
// MODE=0: write C.  MODE=1: KV-pack epilogue -> write Kp (k half) / Vt (v half).
template<int SPLITA, int MODE>
__global__ __launch_bounds__(256) void mma_gemm(
        const float* __restrict__ A, const float* __restrict__ B,
        float* __restrict__ C, int M, int N, int K,
        float* __restrict__ Kp, float* __restrict__ Vt) {
    extern __shared__ float smf[];
    const int PER = SPLITA * ATILE + BTILE;

    int tid = threadIdx.x;
    int w = tid >> 5, lane = tid & 31, g = lane >> 2, t = lane & 3;
    int wm = (w >> 2) * 64, wn = (w & 3) * 32;

    const float* Ab = A + (size_t)(blockIdx.y * 128) * K;
    const float* Bb = B + (size_t)(blockIdx.x * 128);

    int aRow = tid >> 1,  aCol = (tid & 1) * 8;
    int bRow = tid >> 4,  bCol = (tid & 15) * 8;

    float acc[4][4][4];
    #pragma unroll
    for (int mi = 0; mi < 4; mi++)
        #pragma unroll
        for (int nj = 0; nj < 4; nj++)
            #pragma unroll
            for (int q = 0; q < 4; q++) acc[mi][nj][q] = 0.f;

    float4 pa0, pa1, pb0, pb1;
    {
        const float* ap = Ab + (size_t)aRow * K + aCol;
        pa0 = *(const float4*)ap; pa1 = *(const float4*)(ap + 4);
        const float* bp = Bb + (size_t)bRow * N + bCol;
        pb0 = *(const float4*)bp; pb1 = *(const float4*)(bp + 4);
    }
    // store tile 0
    {
        float* base = smf;
        float* AhP = base;
        float* BhP = base + SPLITA * ATILE;
        float4 h0 = make_float4(tf32f(pa0.x), tf32f(pa0.y), tf32f(pa0.z), tf32f(pa0.w));
        float4 h1 = make_float4(tf32f(pa1.x), tf32f(pa1.y), tf32f(pa1.z), tf32f(pa1.w));
        *(float4*)&AhP[aRow * APITCH + aCol]     = h0;
        *(float4*)&AhP[aRow * APITCH + aCol + 4] = h1;
        if (SPLITA == 2) {
            float* AlP = base + ATILE;
            *(float4*)&AlP[aRow * APITCH + aCol] =
                make_float4(tf32f(pa0.x - h0.x), tf32f(pa0.y - h0.y), tf32f(pa0.z - h0.z), tf32f(pa0.w - h0.w));
            *(float4*)&AlP[aRow * APITCH + aCol + 4] =
                make_float4(tf32f(pa1.x - h1.x), tf32f(pa1.y - h1.y), tf32f(pa1.z - h1.z), tf32f(pa1.w - h1.w));
        }
        *(float4*)&BhP[bRow * BPITCH + bCol] =
            make_float4(tf32f(pb0.x), tf32f(pb0.y), tf32f(pb0.z), tf32f(pb0.w));
        *(float4*)&BhP[bRow * BPITCH + bCol + 4] =
            make_float4(tf32f(pb1.x), tf32f(pb1.y), tf32f(pb1.z), tf32f(pb1.w));
    }
    __syncthreads();

    int buf = 0;
    for (int k0 = 0; k0 < K; k0 += 16) {
        bool next = (k0 + 16) < K;
        if (next) {
            const float* ap = Ab + (size_t)aRow * K + (k0 + 16) + aCol;
            pa0 = *(const float4*)ap; pa1 = *(const float4*)(ap + 4);
            const float* bp = Bb + (size_t)(k0 + 16 + bRow) * N + bCol;
            pb0 = *(const float4*)bp; pb1 = *(const float4*)(bp + 4);
        }
        float* base = smf + buf * PER;
        const float* AhP = base;
        const float* AlP = base + ATILE;
        const float* BhP = base + SPLITA * ATILE;
        #pragma unroll
        for (int kk = 0; kk < 2; kk++) {
            int k = kk * 8;
            unsigned aF[4][4], bF[4][2];
            #pragma unroll
            for (int mi = 0; mi < 4; mi++) {
                const float* ap2 = AhP + (wm + mi * 16 + g) * APITCH + k + t;
                aF[mi][0] = __float_as_uint(ap2[0]);
                aF[mi][1] = __float_as_uint(ap2[8 * APITCH]);
                aF[mi][2] = __float_as_uint(ap2[4]);
                aF[mi][3] = __float_as_uint(ap2[8 * APITCH + 4]);
            }
            #pragma unroll
            for (int nj = 0; nj < 4; nj++) {
                const float* bp2 = BhP + (k + t) * BPITCH + wn + nj * 8 + g;
                bF[nj][0] = __float_as_uint(bp2[0]);
                bF[nj][1] = __float_as_uint(bp2[4 * BPITCH]);
            }
            #pragma unroll
            for (int mi = 0; mi < 4; mi++)
                #pragma unroll
                for (int nj = 0; nj < 4; nj++)
                    MMA_TF32(acc[mi][nj], aF[mi], bF[nj][0], bF[nj][1]);
            if (SPLITA == 2) {
                unsigned aL[4][4];
                #pragma unroll
                for (int mi = 0; mi < 4; mi++) {
                    const float* ap2 = AlP + (wm + mi * 16 + g) * APITCH + k + t;
                    aL[mi][0] = __float_as_uint(ap2[0]);
                    aL[mi][1] = __float_as_uint(ap2[8 * APITCH]);
                    aL[mi][2] = __float_as_uint(ap2[4]);
                    aL[mi][3] = __float_as_uint(ap2[8 * APITCH + 4]);
                }
                #pragma unroll
                for (int mi = 0; mi < 4; mi++)
                    #pragma unroll
                    for (int nj = 0; nj < 4; nj++)
                        MMA_TF32(acc[mi][nj], aL[mi], bF[nj][0], bF[nj][1]);
            }
        }
        if (next) {
            float* nb = smf + (buf ^ 1) * PER;
            float* AhP2 = nb;
            float* BhP2 = nb + SPLITA * ATILE;
            float4 h0 = make_float4(tf32f(pa0.x), tf32f(pa0.y), tf32f(pa0.z), tf32f(pa0.w));
            float4 h1 = make_float4(tf32f(pa1.x), tf32f(pa1.y), tf32f(pa1.z), tf32f(pa1.w));
            *(float4*)&AhP2[aRow * APITCH + aCol]     = h0;
            *(float4*)&AhP2[aRow * APITCH + aCol + 4] = h1;
            if (SPLITA == 2) {
                float* AlP2 = nb + ATILE;
                *(float4*)&AlP2[aRow * APITCH + aCol] =
                    make_float4(tf32f(pa0.x - h0.x), tf32f(pa0.y - h0.y), tf32f(pa0.z - h0.z), tf32f(pa0.w - h0.w));
                *(float4*)&AlP2[aRow * APITCH + aCol + 4] =
                    make_float4(tf32f(pa1.x - h1.x), tf32f(pa1.y - h1.y), tf32f(pa1.z - h1.z), tf32f(pa1.w - h1.w));
            }
            *(float4*)&BhP2[bRow * BPITCH + bCol] =
                make_float4(tf32f(pb0.x), tf32f(pb0.y), tf32f(pb0.z), tf32f(pb0.w));
            *(float4*)&BhP2[bRow * BPITCH + bCol + 4] =
                make_float4(tf32f(pb1.x), tf32f(pb1.y), tf32f(pb1.z), tf32f(pb1.w));
            __syncthreads();
            buf ^= 1;
        }
    }

    if (MODE == 0) {
        #pragma unroll
        for (int mi = 0; mi < 4; mi++) {
            int row = blockIdx.y * 128 + wm + mi * 16 + g;
            #pragma unroll
            for (int nj = 0; nj < 4; nj++) {
                int col = blockIdx.x * 128 + wn + nj * 8 + 2 * t;
                *(float2*)&C[(size_t)row * N + col]       = make_float2(acc[mi][nj][0], acc[mi][nj][1]);
                *(float2*)&C[(size_t)(row + 8) * N + col] = make_float2(acc[mi][nj][2], acc[mi][nj][3]);
            }
        }
    } else {
        #pragma unroll
        for (int mi = 0; mi < 4; mi++) {
            int row = blockIdx.y * 128 + wm + mi * 16 + g;
            #pragma unroll
            for (int nj = 0; nj < 4; nj++) {
                int col = blockIdx.x * 128 + wn + nj * 8 + 2 * t;
                int s = col >> 10, h = (col >> 6) & 15, d = col & 63;
                #pragma unroll
                for (int half = 0; half < 2; half++) {
                    int tok = row + half * 8;
                    int b = tok >> 11, n = tok & 2047;
                    int bh = b * HH + h;
                    float v0 = tf32f(acc[mi][nj][half * 2 + 0]);
                    float v1 = tf32f(acc[mi][nj][half * 2 + 1]);
                    if (s == 0) {
                        *(float2*)&Kp[((size_t)bh * NKEYS + n) * DD + d] = make_float2(v0, v1);
                    } else {
                        Vt[((size_t)bh * DD + d)     * NKEYS + n] = v0;
                        Vt[((size_t)bh * DD + d + 1) * NKEYS + n] = v1;
                    }
                }
            }
        }
    }
}

// ---------------- flash attention on tensor cores (tf32 mma.sync) --------------
// v2: grid (N/128, H, B), 128 threads = 4 warps; each warp owns 32 query rows
// (two 16-row A blocks) so every K/V B-fragment load feeds TWO mmas.
// P lives in a private 128-row smem region (dynamic smem total 69.6KB).
__global__ __launch_bounds__(128) void attn_mma_kernel(
        const float* __restrict__ qb,
        const float* __restrict__ Kp,
        const float* __restrict__ Vt,
        float* __restrict__ outb) {
    extern __shared__ float smem[];
    float* Ksm = smem;                    // 64 rows
    float* Vsm = smem + 64 * SPITCH;      // 64 rows
    float* Psm = smem + 128 * SPITCH;     // 128 rows (warp-private 32-row slices)
    int b = blockIdx.z, h = blockIdx.y;
    int tid = threadIdx.x;
    int w = tid >> 5, lane = tid & 31;
    int g = lane >> 2, t = lane & 3;
    int qa = blockIdx.x * 128 + w * 32 + g;   // rows qa, +8, +16, +24

    unsigned qA[2][8][4];
    #pragma unroll
    for (int blk = 0; blk < 2; blk++) {
        const float* q0 = qb + ((size_t)(b * NN + qa + blk * 16)) * (HH * DD) + h * DD;
        const float* q1 = q0 + 8 * (HH * DD);
        #pragma unroll
        for (int kk = 0; kk < 8; kk++) {
            qA[blk][kk][0] = f2tf32(q0[kk * 8 + t]     * 0.125f);
            qA[blk][kk][1] = f2tf32(q1[kk * 8 + t]     * 0.125f);
            qA[blk][kk][2] = f2tf32(q0[kk * 8 + t + 4] * 0.125f);
            qA[blk][kk][3] = f2tf32(q1[kk * 8 + t + 4] * 0.125f);
        }
    }

    const float* Kg = Kp + ((size_t)(b * HH + h)) * NKEYS * DD;
    const float* Vg = Vt + ((size_t)(b * HH + h)) * DD * NKEYS;

    float m[4] = {-1e30f, -1e30f, -1e30f, -1e30f};
    float l[4] = {0.f, 0.f, 0.f, 0.f};
    float oC[2][8][4];
    #pragma unroll
    for (int blk = 0; blk < 2; blk++)
        #pragma unroll
        for (int nt = 0; nt < 8; nt++)
            #pragma unroll
            for (int j = 0; j < 4; j++) oC[blk][nt][j] = 0.f;

    float* Prow[4];
    #pragma unroll
    for (int r = 0; r < 4; r++) Prow[r] = &Psm[(w * 32 + r * 8 + g) * SPITCH];

    for (int tile = 0; tile < NTILES; tile++) {
        int tb = tile * 64;
        __syncthreads();
        #pragma unroll
        for (int i = 0; i < 8; i++) {
            int idx = tid + i * 128;
            int r = idx >> 4, c = (idx & 15) * 4;
            *(float4*)&Ksm[r * SPITCH + c] = *(const float4*)&Kg[(size_t)(tb + r) * DD + c];
            *(float4*)&Vsm[r * SPITCH + c] = *(const float4*)&Vg[(size_t)r * NKEYS + tb + c];
        }
        __syncthreads();

        // ---- S = Q * K^T for both row blocks (shared K fragments) ----
        float sC[2][8][4];
        #pragma unroll
        for (int blk = 0; blk < 2; blk++)
            #pragma unroll
            for (int nt = 0; nt < 8; nt++)
                #pragma unroll
                for (int j = 0; j < 4; j++) sC[blk][nt][j] = 0.f;
        #pragma unroll
        for (int kk = 0; kk < 8; kk++) {
            #pragma unroll
            for (int nt = 0; nt < 8; nt++) {
                const float* kr = &Ksm[(nt * 8 + g) * SPITCH + kk * 8 + t];
                unsigned b0 = __float_as_uint(kr[0]);
                unsigned b1 = __float_as_uint(kr[4]);
                MMA_TF32(sC[0][nt], qA[0][kk], b0, b1);
                MMA_TF32(sC[1][nt], qA[1][kk], b0, b1);
            }
        }

        // ---- pad mask (only the last tile has pad keys) ----
        if (tile == NTILES - 1) {
            int lim = LIMIT - tb;
            #pragma unroll
            for (int nt = 0; nt < 8; nt++) {
                int c0 = nt * 8 + 2 * t, c1 = c0 + 1;
                #pragma unroll
                for (int blk = 0; blk < 2; blk++) {
                    if (c0 >= lim) { sC[blk][nt][0] = -1e30f; sC[blk][nt][2] = -1e30f; }
                    if (c1 >= lim) { sC[blk][nt][1] = -1e30f; sC[blk][nt][3] = -1e30f; }
                }
            }
        }

        // ---- online softmax for 4 row groups ----
        #pragma unroll
        for (int blk = 0; blk < 2; blk++) {
            float tmax0 = -1e30f, tmax1 = -1e30f;
            #pragma unroll
            for (int nt = 0; nt < 8; nt++) {
                tmax0 = fmaxf(tmax0, fmaxf(sC[blk][nt][0], sC[blk][nt][1]));
                tmax1 = fmaxf(tmax1, fmaxf(sC[blk][nt][2], sC[blk][nt][3]));
            }
            tmax0 = fmaxf(tmax0, __shfl_xor_sync(0xffffffffu, tmax0, 1));
            tmax0 = fmaxf(tmax0, __shfl_xor_sync(0xffffffffu, tmax0, 2));
            tmax1 = fmaxf(tmax1, __shfl_xor_sync(0xffffffffu, tmax1, 1));
            tmax1 = fmaxf(tmax1, __shfl_xor_sync(0xffffffffu, tmax1, 2));

            int r0 = blk * 2, r1 = blk * 2 + 1;
            float mn0 = fmaxf(m[r0], tmax0), mn1 = fmaxf(m[r1], tmax1);
            float corr0 = __expf(m[r0] - mn0), corr1 = __expf(m[r1] - mn1);
            m[r0] = mn0; m[r1] = mn1;

            float ps0 = 0.f, ps1 = 0.f;
            #pragma unroll
            for (int nt = 0; nt < 8; nt++) {
                float p0 = __expf(sC[blk][nt][0] - mn0), p1 = __expf(sC[blk][nt][1] - mn0);
                float p2 = __expf(sC[blk][nt][2] - mn1), p3 = __expf(sC[blk][nt][3] - mn1);
                ps0 += p0 + p1; ps1 += p2 + p3;
                *(float2*)&Prow[r0][nt * 8 + 2 * t] = make_float2(tf32f(p0), tf32f(p1));
                *(float2*)&Prow[r1][nt * 8 + 2 * t] = make_float2(tf32f(p2), tf32f(p3));
                oC[blk][nt][0] *= corr0; oC[blk][nt][1] *= corr0;
                oC[blk][nt][2] *= corr1; oC[blk][nt][3] *= corr1;
            }
            l[r0] = l[r0] * corr0 + ps0;
            l[r1] = l[r1] * corr1 + ps1;
        }
        __syncwarp();                  // P rows are warp-private

        // ---- O += P * V for both blocks (shared V fragments) ----
        #pragma unroll
        for (int kk = 0; kk < 8; kk++) {
            unsigned a0[4], a1[4];
            a0[0] = __float_as_uint(Prow[0][kk * 8 + t]);
            a0[1] = __float_as_uint(Prow[1][kk * 8 + t]);
            a0[2] = __float_as_uint(Prow[0][kk * 8 + t + 4]);
            a0[3] = __float_as_uint(Prow[1][kk * 8 + t + 4]);
            a1[0] = __float_as_uint(Prow[2][kk * 8 + t]);
            a1[1] = __float_as_uint(Prow[3][kk * 8 + t]);
            a1[2] = __float_as_uint(Prow[2][kk * 8 + t + 4]);
            a1[3] = __float_as_uint(Prow[3][kk * 8 + t + 4]);
            #pragma unroll
            for (int nd = 0; nd < 8; nd++) {
                const float* vr = &Vsm[(nd * 8 + g) * SPITCH + kk * 8 + t];
                unsigned b0 = __float_as_uint(vr[0]);
                unsigned b1 = __float_as_uint(vr[4]);
                MMA_TF32(oC[0][nd], a0, b0, b1);
                MMA_TF32(oC[1][nd], a1, b0, b1);
            }
        }
    }

    // ---- epilogue ----
    #pragma unroll
    for (int r = 0; r < 4; r++) {
        l[r] += __shfl_xor_sync(0xffffffffu, l[r], 1);
        l[r] += __shfl_xor_sync(0xffffffffu, l[r], 2);
    }
    #pragma unroll
    for (int blk = 0; blk < 2; blk++) {
        float inv0 = 1.f / l[blk * 2], inv1 = 1.f / l[blk * 2 + 1];
        float* o0 = outb + ((size_t)(b * NN + qa + blk * 16)) * (HH * DD) + h * DD;
        float* o1 = o0 + 8 * (HH * DD);
        #pragma unroll
        for (int nt = 0; nt < 8; nt++) {
            *(float2*)&o0[nt * 8 + 2 * t] = make_float2(oC[blk][nt][0] * inv0, oC[blk][nt][1] * inv0);
            *(float2*)&o1[nt * 8 + 2 * t] = make_float2(oC[blk][nt][2] * inv1, oC[blk][nt][3] * inv1);
        }
    }
}

// ---------------- host launcher ------------------------------------------------
extern "C" void kernel_launch(void* const* d_in, const int* in_sizes, int n_in,
                              void* d_out, int out_size) {
    const float* x        = (const float*)d_in[0];
    const float* c_emb    = (const float*)d_in[1];
    const float* ln_g     = (const float*)d_in[2];
    const float* ln_b     = (const float*)d_in[3];
    const float* ctx_ln_g = (const float*)d_in[4];
    const float* ctx_ln_b = (const float*)d_in[5];
    const float* W_ctx    = (const float*)d_in[6];
    const float* b_ctx    = (const float*)d_in[7];
    const float* W_q      = (const float*)d_in[8];
    const float* W_kv     = (const float*)d_in[9];
    const float* null_kv  = (const float*)d_in[10];
    const float* W_out    = (const float*)d_in[11];
    const float* out_ln_g = (const float*)d_in[12];
    const float* out_ln_b = (const float*)d_in[13];
    float* out = (float*)d_out;

    float *xn, *qb, *kext, *vext, *kt, *vt, *attn, *proj;
    cudaGetSymbolAddress((void**)&xn,   g_xn);
    cudaGetSymbolAddress((void**)&qb,   g_q);
    cudaGetSymbolAddress((void**)&kext, g_kext);
    cudaGetSymbolAddress((void**)&vext, g_vext);
    cudaGetSymbolAddress((void**)&kt,   g_kt);
    cudaGetSymbolAddress((void**)&vt,   g_vt);
    cudaGetSymbolAddress((void**)&attn, g_attn);
    cudaGetSymbolAddress((void**)&proj, g_proj);

    const int smem1 = 2 * (1 * ATILE + BTILE) * 4;   // 37888 B
    const int smem2 = 2 * (2 * ATILE + BTILE) * 4;   // 58368 B
    const int smemA = 256 * SPITCH * 4;              // 69632 B (K+V+P)
    cudaFuncSetAttribute((const void*)mma_gemm<1,0>, cudaFuncAttributeMaxDynamicSharedMemorySize, smem1);
    cudaFuncSetAttribute((const void*)mma_gemm<1,1>, cudaFuncAttributeMaxDynamicSharedMemorySize, smem1);
    cudaFuncSetAttribute((const void*)mma_gemm<2,0>, cudaFuncAttributeMaxDynamicSharedMemorySize, smem2);
    cudaFuncSetAttribute((const void*)attn_mma_kernel, cudaFuncAttributeMaxDynamicSharedMemorySize, smemA);

    ln_kernel<<<ROWS, 256>>>(x, xn, ln_g, ln_b, IND);
    ctx_kernel<<<BB * MM, 256>>>(c_emb, ctx_ln_g, ctx_ln_b, W_ctx, b_ctx, kext, vext);
    pack_ext_kernel<<<(BB * HH * (NKEYS - NN) * DD) / 256, 256>>>(kext, vext, null_kv, kt, vt);
    // Q projection
    mma_gemm<1,0><<<dim3((HH * DD) / 128, ROWS / 128), 256, smem1>>>(
        xn, W_q, qb, ROWS, HH * DD, IND, nullptr, nullptr);
    // KV projection with fused pack epilogue (writes kt / vt directly)
    mma_gemm<1,1><<<dim3(KVW / 128, ROWS / 128), 256, smem1>>>(
        xn, W_kv, nullptr, ROWS, KVW, IND, kt, vt);
    // attention (4 warps, 32 q-rows per warp)
    attn_mma_kernel<<<dim3(NN / 128, HH, BB), 128, smemA>>>(qb, kt, vt, attn);
    // output projection (split-A for accuracy)
    mma_gemm<2,0><<<dim3(IND / 128, ROWS / 128), 256, smem2>>>(
        attn, W_out, proj, ROWS, IND, IND, nullptr, nullptr);
    ln_kernel<<<ROWS, 256>>>(proj, out, out_ln_g, out_ln_b, IND);
}